// round 11
// baseline (speedup 1.0000x reference)
#include <cuda_runtime.h>
#include <math.h>
#include <stdint.h>

#define NATOMS 100000
#define MNBR   12
#define NEDGE  (NATOMS*MNBR)
#define ORIG   92
#define NBRD   41
#define FDIM   64
#define HFD    128
#define NCONVL 3
#define BQ     500
#define NPC    200
#define Y0C    0.28209479177387814f
#define TPN    0.125f
#define EPSB   1e-5f

#define NTILES (NEDGE/64)     // 18750
#define NBLK   444            // 148 SMs * 3

// ---------------- scratch (no cudaMalloc allowed) ----------------
__device__ float g_x[NATOMS*FDIM];
__device__ float g_y[NATOMS*FDIM];
__device__ float g_w0[3*NEDGE];
__device__ float g_bnsum[NCONVL*2*FDIM];
__device__ float g_Wpad[48*128];
__device__ float g_Wctf[NCONVL*64*68];   // conv W, tf32, exact smem layout [col*68+k]
__device__ float g_EWhi[64*100];         // embed W hi, [col*100+k]
__device__ float g_EWlo[64*100];         // embed W lo
__device__ float g_epib1[128];
__device__ float g_epiw2[128];
__device__ float g_epir0[3];

__device__ __forceinline__ float softplus_f(float z) {
    float t = fabsf(z);
    float e = __expf(-t);
    return fmaxf(z, 0.0f) + __logf(1.0f + e);
}

__device__ __forceinline__ uint32_t to_tf32(float v) {
    uint32_t t;
    asm("cvt.rna.tf32.f32 %0, %1;" : "=r"(t) : "f"(v));
    return t;
}

__device__ __forceinline__ void mma_tf32(float& d0, float& d1, float& d2, float& d3,
                                         uint32_t a0, uint32_t a1, uint32_t a2, uint32_t a3,
                                         uint32_t b0, uint32_t b1) {
    asm volatile("mma.sync.aligned.m16n8k8.row.col.f32.tf32.tf32.f32 "
                 "{%0,%1,%2,%3}, {%4,%5,%6,%7}, {%8,%9}, {%0,%1,%2,%3};"
                 : "+f"(d0), "+f"(d1), "+f"(d2), "+f"(d3)
                 : "r"(a0), "r"(a1), "r"(a2), "r"(a3), "r"(b0), "r"(b1));
}

// ============ setup: all weight images + epilogue consts + bnsum zero ========
__global__ void setup_kernel(const float* __restrict__ rW1, const float* __restrict__ rb1,
                             const float* __restrict__ rW2, const float* __restrict__ rb2,
                             const float* __restrict__ tpW, const float* __restrict__ embW)
{
    const int tid = threadIdx.x;   // 256
    for (int i = tid; i < 48*128; i += 256) {
        int k = i >> 7, j = i & 127;
        float v = 0.0f;
        if (k < 41 && j < 123) {
            int l = j / 41, jj = j - l*41;
            v = rW1[(l*41 + k)*41 + jj];
        }
        g_Wpad[i] = __uint_as_float(to_tf32(v));
    }
    for (int i = tid; i < NCONVL*64*68; i += 256) {
        int l = i / (64*68), r = i - l*(64*68);
        int col = r / 68, k = r - col*68;
        float v = (k < 64) ? tpW[l*4096 + k*64 + col] * TPN : 0.0f;
        g_Wctf[i] = __uint_as_float(to_tf32(v));
    }
    // embed W split: hi = tf32(w), lo = tf32(w - hi); [col*100 + k], k pad 92..99
    for (int i = tid; i < 64*100; i += 256) {
        int col = i / 100, k = i - col*100;
        float v = (k < 92) ? embW[k*64 + col] : 0.0f;
        float hi = __uint_as_float(to_tf32(v));
        g_EWhi[i] = hi;
        g_EWlo[i] = __uint_as_float(to_tf32(v - hi));
    }
    if (tid < 128) {
        float b1 = 0.0f, w2 = 0.0f;
        if (tid < 123) {
            int l = tid / 41, jj = tid - l*41;
            b1 = rb1[l*41 + jj];
            w2 = rW2[(l*41 + jj)*9] * (Y0C / (float)MNBR);
        }
        g_epib1[tid] = b1;
        g_epiw2[tid] = w2;
    }
    if (tid < 3) g_epir0[tid] = rb2[tid*9] * (Y0C / (float)MNBR);
    for (int i = tid; i < NCONVL*2*FDIM; i += 256) g_bnsum[i] = 0.0f;
}

// ============ edge kernel: persistent, double-buffered, mma.sync tf32 ========
__global__ __launch_bounds__(128, 3) void edge_mma_kernel(const float* __restrict__ nbr_fea)
{
    __shared__ float sA[2][64*52];
    __shared__ float sRed[4][64*3];
    const int tid  = threadIdx.x;
    const int wid  = tid >> 5, lane = tid & 31;
    const int g    = lane >> 2, q = lane & 3;
    const int bid  = blockIdx.x;

    const int wbase = wid * 32;
    uint32_t bf[6][4][2];
    #pragma unroll
    for (int k = 0; k < 6; k++)
        #pragma unroll
        for (int nt = 0; nt < 4; nt++) {
            int col = wbase + nt*8 + g;
            bf[k][nt][0] = __float_as_uint(g_Wpad[(k*8 + q)*128 + col]);
            bf[k][nt][1] = __float_as_uint(g_Wpad[(k*8 + q + 4)*128 + col]);
        }
    float b1a[4], b1b[4], w2a[4], w2b[4];
    int lyA[4], lyB[4];
    #pragma unroll
    for (int nt = 0; nt < 4; nt++) {
        int ja = wbase + nt*8 + q*2, jb = ja + 1;
        b1a[nt] = g_epib1[ja]; b1b[nt] = g_epib1[jb];
        w2a[nt] = g_epiw2[ja]; w2b[nt] = g_epiw2[jb];
        lyA[nt] = (ja < 41) ? 0 : ((ja < 82) ? 1 : 2);
        lyB[nt] = (jb < 41) ? 0 : ((jb < 82) ? 1 : 2);
    }
    const float r0c = g_epir0[0], r1c = g_epir0[1], r2c = g_epir0[2];

    for (int i = tid; i < 64*7; i += 128) {
        int r = i / 7, c = 41 + (i - r*7);
        sA[0][r*52 + c] = 0.0f;
        sA[1][r*52 + c] = 0.0f;
    }
    {
        const float* src = nbr_fea + (size_t)bid * 2624;
        for (int i = tid; i < 2624; i += 128) {
            int r = i / 41, c = i - r*41;
            sA[0][r*52 + c] = __uint_as_float(to_tf32(src[i]));
        }
    }

    int cur = 0;
    for (int t = bid; t < NTILES; t += NBLK) {
        const int tn = t + NBLK;
        const bool have_next = (tn < NTILES);
        __syncthreads();

        float pf[21];
        if (have_next) {
            const float* src = nbr_fea + (size_t)tn * 2624;
            #pragma unroll
            for (int j = 0; j < 20; j++) pf[j] = src[tid + j*128];
            if (tid < 64) pf[20] = src[tid + 2560];
        }

        const float* A = sA[cur];
        #pragma unroll
        for (int m = 0; m < 4; m++) {
            float d[4][4];
            #pragma unroll
            for (int nt = 0; nt < 4; nt++)
                #pragma unroll
                for (int f = 0; f < 4; f++) d[nt][f] = 0.0f;

            const int row0 = m*16 + g, row1 = row0 + 8;
            #pragma unroll
            for (int k = 0; k < 6; k++) {
                uint32_t a0 = __float_as_uint(A[row0*52 + k*8 + q]);
                uint32_t a1 = __float_as_uint(A[row1*52 + k*8 + q]);
                uint32_t a2 = __float_as_uint(A[row0*52 + k*8 + q + 4]);
                uint32_t a3 = __float_as_uint(A[row1*52 + k*8 + q + 4]);
                #pragma unroll
                for (int nt = 0; nt < 4; nt++)
                    mma_tf32(d[nt][0], d[nt][1], d[nt][2], d[nt][3],
                             a0, a1, a2, a3, bf[k][nt][0], bf[k][nt][1]);
            }

            float aA0 = 0.0f, aA1 = 0.0f, aA2 = 0.0f;
            float aB0 = 0.0f, aB1 = 0.0f, aB2 = 0.0f;
            #pragma unroll
            for (int nt = 0; nt < 4; nt++) {
                float v00 = softplus_f(d[nt][0] + b1a[nt]) * w2a[nt];
                float v01 = softplus_f(d[nt][1] + b1b[nt]) * w2b[nt];
                float v10 = softplus_f(d[nt][2] + b1a[nt]) * w2a[nt];
                float v11 = softplus_f(d[nt][3] + b1b[nt]) * w2b[nt];
                if (lyA[nt] == 0) { aA0 += v00; aB0 += v10; }
                else if (lyA[nt] == 1) { aA1 += v00; aB1 += v10; }
                else { aA2 += v00; aB2 += v10; }
                if (lyB[nt] == 0) { aA0 += v01; aB0 += v11; }
                else if (lyB[nt] == 1) { aA1 += v01; aB1 += v11; }
                else { aA2 += v01; aB2 += v11; }
            }
            #pragma unroll
            for (int s = 1; s <= 2; s <<= 1) {
                aA0 += __shfl_xor_sync(0xffffffffu, aA0, s);
                aA1 += __shfl_xor_sync(0xffffffffu, aA1, s);
                aA2 += __shfl_xor_sync(0xffffffffu, aA2, s);
                aB0 += __shfl_xor_sync(0xffffffffu, aB0, s);
                aB1 += __shfl_xor_sync(0xffffffffu, aB1, s);
                aB2 += __shfl_xor_sync(0xffffffffu, aB2, s);
            }
            if (q == 0) {
                sRed[wid][row0*3 + 0] = aA0;
                sRed[wid][row0*3 + 1] = aA1;
                sRed[wid][row0*3 + 2] = aA2;
                sRed[wid][row1*3 + 0] = aB0;
                sRed[wid][row1*3 + 1] = aB1;
                sRed[wid][row1*3 + 2] = aB2;
            }
        }
        __syncthreads();

        const int base = t*64;
        for (int i = tid; i < 64*3; i += 128) {
            int row = i / 3, ly = i - row*3;
            float s = sRed[0][i] + sRed[1][i] + sRed[2][i] + sRed[3][i];
            float r0 = (ly == 0) ? r0c : ((ly == 1) ? r1c : r2c);
            g_w0[ly*NEDGE + base + row] = s + r0;
        }

        if (have_next) {
            float* B = sA[cur ^ 1];
            #pragma unroll
            for (int j = 0; j < 20; j++) {
                int idx = tid + j*128;
                int r = idx / 41, c = idx - r*41;
                B[r*52 + c] = __uint_as_float(to_tf32(pf[j]));
            }
            if (tid < 64) {
                int idx = tid + 2560;
                int r = idx / 41, c = idx - r*41;
                B[r*52 + c] = __uint_as_float(to_tf32(pf[20]));
            }
        }
        cur ^= 1;
    }
}

// =============== embedding via 3xTF32 mma: x = A @ W + b =====================
// x ~= Ahi@Whi + Alo@Whi + Ahi@Wlo  (error ~2^-22)
__global__ __launch_bounds__(256, 2) void embed_mma_kernel(
    const float* __restrict__ A, const float* __restrict__ bias)
{
    extern __shared__ float sm[];
    float* sAhi = sm;                 // [64*100]
    float* sAlo = sAhi + 6400;
    float* sWhi = sAlo + 6400;        // [col*100 + k]
    float* sWlo = sWhi + 6400;
    float* sB   = sWlo + 6400;        // [64]
    const int tid = threadIdx.x;
    const int row0 = blockIdx.x * 64;

    // stage W images (pure float4 copy)
    {
        const float4* shi = (const float4*)g_EWhi;
        const float4* slo = (const float4*)g_EWlo;
        float4* dhi = (float4*)sWhi;
        float4* dlo = (float4*)sWlo;
        for (int i = tid; i < 1600; i += 256) { dhi[i] = shi[i]; dlo[i] = slo[i]; }
    }
    if (tid < 64) sB[tid] = bias[tid];
    // stage A hi/lo (pad k 92..99 with zero)
    for (int i = tid; i < 6400; i += 256) {
        int r = i / 100, k = i - r*100;
        int row = row0 + r;
        float v = (k < 92 && row < NATOMS) ? A[row*92 + k] : 0.0f;
        float hi = __uint_as_float(to_tf32(v));
        sAhi[i] = hi;
        sAlo[i] = __uint_as_float(to_tf32(v - hi));
    }
    __syncthreads();

    const int lane = tid & 31, w = tid >> 5;
    const int mt = w & 3, nh = w >> 2;
    const int g = lane >> 2, q = lane & 3;
    const int ra = mt*16 + g, rb = ra + 8;

    float d[4][4];
    #pragma unroll
    for (int nt = 0; nt < 4; nt++)
        #pragma unroll
        for (int f = 0; f < 4; f++) d[nt][f] = 0.0f;

    #pragma unroll
    for (int pass = 0; pass < 3; pass++) {
        const float* Ap = (pass == 1) ? sAlo : sAhi;
        const float* Wp = (pass == 2) ? sWlo : sWhi;
        #pragma unroll
        for (int k = 0; k < 12; k++) {
            uint32_t a0 = __float_as_uint(Ap[ra*100 + k*8 + q]);
            uint32_t a1 = __float_as_uint(Ap[rb*100 + k*8 + q]);
            uint32_t a2 = __float_as_uint(Ap[ra*100 + k*8 + q + 4]);
            uint32_t a3 = __float_as_uint(Ap[rb*100 + k*8 + q + 4]);
            #pragma unroll
            for (int nt = 0; nt < 4; nt++) {
                const int col = nh*32 + nt*8 + g;
                uint32_t b0 = __float_as_uint(Wp[col*100 + k*8 + q]);
                uint32_t b1 = __float_as_uint(Wp[col*100 + k*8 + q + 4]);
                mma_tf32(d[nt][0], d[nt][1], d[nt][2], d[nt][3], a0, a1, a2, a3, b0, b1);
            }
        }
    }

    const int gra = row0 + ra, grb = row0 + rb;
    #pragma unroll
    for (int nt = 0; nt < 4; nt++) {
        const int ja = nh*32 + nt*8 + q*2;
        if (gra < NATOMS)
            *(float2*)(g_x + gra*64 + ja) = make_float2(d[nt][0] + sB[ja], d[nt][1] + sB[ja+1]);
        if (grb < NATOMS)
            *(float2*)(g_x + grb*64 + ja) = make_float2(d[nt][2] + sB[ja], d[nt][3] + sB[ja+1]);
    }
}

// ====== fused layer kernel: float4 gather + tf32 mma GEMM + stats ============
__global__ __launch_bounds__(256, 4) void conv_fused_kernel(
    const int* __restrict__ nbr_idx, int l)
{
    __shared__ float sS[64*68];
    __shared__ float sWc[64*68];
    __shared__ int   sIdx[64*12];
    __shared__ float sW0[64*12];
    __shared__ float sStat[128];
    const int tid = threadIdx.x;
    const int row0 = blockIdx.x * 64;

    {
        const float4* src = (const float4*)(g_Wctf + l*(64*68));
        float4* dst = (float4*)sWc;
        for (int i = tid; i < 64*68/4; i += 256) dst[i] = src[i];
    }
    if (tid < 128) sStat[tid] = 0.0f;

    {
        const float* w0l = g_w0 + (size_t)l*NEDGE;
        for (int i = tid; i < 64*12; i += 256) {
            int n = row0 + i/12;
            bool v = (n < NATOMS);
            sIdx[i] = v ? nbr_idx[row0*12 + i] : 0;
            sW0[i]  = v ? w0l[row0*12 + i] : 0.0f;
        }
    }
    __syncthreads();

    {
        const int lane = tid & 31, w = tid >> 5;
        const int half = lane >> 4, q4 = lane & 15;
        #pragma unroll
        for (int p = 0; p < 4; p++) {
            const int r = w*8 + p*2 + half;
            float4 acc = make_float4(0.0f, 0.0f, 0.0f, 0.0f);
            #pragma unroll
            for (int m = 0; m < 12; m++) {
                const int nb = sIdx[r*12 + m];
                const float wv = sW0[r*12 + m];
                float4 v = *(const float4*)(g_x + nb*64 + q4*4);
                acc.x = fmaf(wv, v.x, acc.x);
                acc.y = fmaf(wv, v.y, acc.y);
                acc.z = fmaf(wv, v.z, acc.z);
                acc.w = fmaf(wv, v.w, acc.w);
            }
            uint4 t;
            t.x = to_tf32(acc.x); t.y = to_tf32(acc.y);
            t.z = to_tf32(acc.z); t.w = to_tf32(acc.w);
            *(uint4*)(&sS[r*68 + q4*4]) = t;
        }
    }
    __syncthreads();

    const int lane = tid & 31, w = tid >> 5;
    const int mt = w & 3, nh = w >> 2;
    const int g = lane >> 2, q = lane & 3;
    const int ra = mt*16 + g, rb = ra + 8;

    float d[4][4];
    #pragma unroll
    for (int nt = 0; nt < 4; nt++)
        #pragma unroll
        for (int f = 0; f < 4; f++) d[nt][f] = 0.0f;

    #pragma unroll
    for (int k = 0; k < 8; k++) {
        uint32_t a0 = __float_as_uint(sS[ra*68 + k*8 + q]);
        uint32_t a1 = __float_as_uint(sS[rb*68 + k*8 + q]);
        uint32_t a2 = __float_as_uint(sS[ra*68 + k*8 + q + 4]);
        uint32_t a3 = __float_as_uint(sS[rb*68 + k*8 + q + 4]);
        #pragma unroll
        for (int nt = 0; nt < 4; nt++) {
            const int col = nh*32 + nt*8 + g;
            uint32_t b0 = __float_as_uint(sWc[col*68 + k*8 + q]);
            uint32_t b1 = __float_as_uint(sWc[col*68 + k*8 + q + 4]);
            mma_tf32(d[nt][0], d[nt][1], d[nt][2], d[nt][3], a0, a1, a2, a3, b0, b1);
        }
    }

    const int gra = row0 + ra, grb = row0 + rb;
    const bool va = gra < NATOMS, vb = grb < NATOMS;
    float s0[4], s1[4], q0[4], q1[4];
    #pragma unroll
    for (int nt = 0; nt < 4; nt++) {
        const int ja = nh*32 + nt*8 + q*2;
        float o00 = 0.0f, o01 = 0.0f, o10 = 0.0f, o11 = 0.0f;
        if (va) {
            float2 xv = *(const float2*)(g_x + gra*64 + ja);
            o00 = d[nt][0] + xv.x;
            o01 = d[nt][1] + xv.y;
            *(float2*)(g_y + gra*64 + ja) = make_float2(o00, o01);
        }
        if (vb) {
            float2 xv = *(const float2*)(g_x + grb*64 + ja);
            o10 = d[nt][2] + xv.x;
            o11 = d[nt][3] + xv.y;
            *(float2*)(g_y + grb*64 + ja) = make_float2(o10, o11);
        }
        s0[nt] = o00 + o10;
        s1[nt] = o01 + o11;
        q0[nt] = o00*o00 + o10*o10;
        q1[nt] = o01*o01 + o11*o11;
    }
    #pragma unroll
    for (int sft = 4; sft <= 16; sft <<= 1) {
        #pragma unroll
        for (int nt = 0; nt < 4; nt++) {
            s0[nt] += __shfl_xor_sync(0xffffffffu, s0[nt], sft);
            s1[nt] += __shfl_xor_sync(0xffffffffu, s1[nt], sft);
            q0[nt] += __shfl_xor_sync(0xffffffffu, q0[nt], sft);
            q1[nt] += __shfl_xor_sync(0xffffffffu, q1[nt], sft);
        }
    }
    if (g == 0) {
        #pragma unroll
        for (int nt = 0; nt < 4; nt++) {
            const int ja = nh*32 + nt*8 + q*2;
            atomicAdd(&sStat[ja],          s0[nt]);
            atomicAdd(&sStat[ja + 1],      s1[nt]);
            atomicAdd(&sStat[64 + ja],     q0[nt]);
            atomicAdd(&sStat[64 + ja + 1], q1[nt]);
        }
    }
    __syncthreads();
    if (tid < 128) atomicAdd(&g_bnsum[l*128 + tid], sStat[tid]);
}

// =============== BN apply + softplus -> new x (layers 0,1) ===================
__global__ void bn_kernel(const float* __restrict__ gamma, const float* __restrict__ beta, int l)
{
    __shared__ float ssc[64], ssh[64];
    const int tid = threadIdx.x;  // 256
    if (tid < 64) {
        float mu  = g_bnsum[l*128 + tid] * (1.0f/NATOMS);
        float var = g_bnsum[l*128 + 64 + tid] * (1.0f/NATOMS) - mu*mu;
        float sc  = gamma[l*64 + tid] * rsqrtf(var + EPSB);
        ssc[tid] = sc;
        ssh[tid] = beta[l*64 + tid] - mu*sc;
    }
    __syncthreads();
    const int total4 = NATOMS*FDIM/4;
    #pragma unroll 4
    for (int i = blockIdx.x*256 + tid; i < total4; i += gridDim.x*256) {
        float4 v = ((const float4*)g_y)[i];
        int c = (i & 15) << 2;
        v.x = softplus_f(fmaf(ssc[c+0], v.x, ssh[c+0]));
        v.y = softplus_f(fmaf(ssc[c+1], v.y, ssh[c+1]));
        v.z = softplus_f(fmaf(ssc[c+2], v.z, ssh[c+2]));
        v.w = softplus_f(fmaf(ssc[c+3], v.w, ssh[c+3]));
        ((float4*)g_x)[i] = v;
    }
}

// =============== head: fused BN(layer2) + pooling + MLP ======================
__global__ __launch_bounds__(128) void head_kernel(
    const int* __restrict__ cidx, const float* __restrict__ fcW, const float* __restrict__ fcb,
    const float* __restrict__ outW, const float* __restrict__ outb,
    const float* __restrict__ gamma, const float* __restrict__ beta,
    float* __restrict__ out)
{
    __shared__ float ssc[64], ssh[64];
    __shared__ float spart[128];
    __shared__ float crys[64];
    __shared__ float hred[128];
    const int b = blockIdx.x, tid = threadIdx.x;
    const int f = tid & 63, half = tid >> 6;
    if (tid < 64) {
        float mu  = g_bnsum[2*128 + tid] * (1.0f/NATOMS);
        float var = g_bnsum[2*128 + 64 + tid] * (1.0f/NATOMS) - mu*mu;
        float sc  = gamma[2*64 + tid] * rsqrtf(var + EPSB);
        ssc[tid] = sc;
        ssh[tid] = beta[2*64 + tid] - mu*sc;
    }
    __syncthreads();
    const float sc = ssc[f], sh = ssh[f];
    const int* ci = cidx + b*NPC + half*(NPC/2);
    float a = 0.0f;
    #pragma unroll 4
    for (int i = 0; i < NPC/2; i++)
        a += softplus_f(fmaf(sc, g_y[ci[i]*64 + f], sh));
    spart[tid] = a;
    __syncthreads();
    if (tid < 64) crys[tid] = (spart[tid] + spart[tid + 64]) * (1.0f/NPC);
    __syncthreads();
    float acc = fcb[tid];
    #pragma unroll 8
    for (int k = 0; k < 64; k++) acc = fmaf(crys[k], fcW[k*128 + tid], acc);
    float h = softplus_f(acc);
    out[BQ + b*HFD + tid] = h;
    hred[tid] = h * outW[tid];
    __syncthreads();
    for (int sft = 64; sft > 0; sft >>= 1) {
        if (tid < sft) hred[tid] += hred[tid + sft];
        __syncthreads();
    }
    if (tid == 0) out[b] = hred[0] + outb[0];
}

// ============================================================================
extern "C" void kernel_launch(void* const* d_in, const int* in_sizes, int n_in,
                              void* d_out, int out_size)
{
    const float* atom_fea = (const float*)d_in[0];
    const float* nbr_fea  = (const float*)d_in[1];
    /* d_in[2] = pos (unused: only Y_0 path contributes) */
    const float* emb_W    = (const float*)d_in[3];
    const float* emb_b    = (const float*)d_in[4];
    const float* rW1      = (const float*)d_in[5];
    const float* rb1      = (const float*)d_in[6];
    const float* rW2      = (const float*)d_in[7];
    const float* rb2      = (const float*)d_in[8];
    const float* tpW      = (const float*)d_in[9];
    const float* bn_gamma = (const float*)d_in[10];
    const float* bn_beta  = (const float*)d_in[11];
    const float* fc_W     = (const float*)d_in[12];
    const float* fc_b     = (const float*)d_in[13];
    const float* out_W    = (const float*)d_in[14];
    const float* out_b    = (const float*)d_in[15];
    const int*   nbr_idx  = (const int*)d_in[16];
    const int*   cidx     = (const int*)d_in[17];
    float* out = (float*)d_out;

    const int embed_smem = (4*6400 + 64) * (int)sizeof(float);   // 102656 B
    cudaFuncSetAttribute(embed_mma_kernel, cudaFuncAttributeMaxDynamicSharedMemorySize, embed_smem);

    setup_kernel<<<1, 256>>>(rW1, rb1, rW2, rb2, tpW, emb_W);
    embed_mma_kernel<<<(NATOMS + 63)/64, 256, embed_smem>>>(atom_fea, emb_b);
    edge_mma_kernel<<<NBLK, 128>>>(nbr_fea);
    for (int l = 0; l < NCONVL; l++) {
        conv_fused_kernel<<<(NATOMS + 63)/64, 256>>>(nbr_idx, l);
        if (l < 2) bn_kernel<<<1184, 256>>>(bn_gamma, bn_beta, l);
    }
    head_kernel<<<BQ, 128>>>(cidx, fc_W, fc_b, out_W, out_b, bn_gamma, bn_beta, out);
}

// round 12
// speedup vs baseline: 1.5394x; 1.5394x over previous
#include <cuda_runtime.h>
#include <math.h>
#include <stdint.h>

#define NATOMS 100000
#define MNBR   12
#define NEDGE  (NATOMS*MNBR)
#define ORIG   92
#define NBRD   41
#define FDIM   64
#define HFD    128
#define NCONVL 3
#define BQ     500
#define NPC    200
#define Y0C    0.28209479177387814f
#define TPN    0.125f
#define EPSB   1e-5f

#define NTILES (NEDGE/64)     // 18750
#define NBLK   444            // 148 SMs * 3

// ---------------- scratch (no cudaMalloc allowed) ----------------
__device__ float g_x[NATOMS*FDIM];
__device__ float g_y[NATOMS*FDIM];
__device__ float g_w0[3*NEDGE];
__device__ float g_bnsum[NCONVL*2*FDIM];
__device__ float g_Wpad[48*128];
__device__ float g_Wctf[NCONVL*64*68];   // conv W, tf32, exact smem layout [col*68+k]
__device__ float g_epib1[128];
__device__ float g_epiw2[128];
__device__ float g_epir0[3];

__device__ __forceinline__ float softplus_f(float z) {
    float t = fabsf(z);
    float e = __expf(-t);
    return fmaxf(z, 0.0f) + __logf(1.0f + e);
}

#define FFMA2(acc, w, x) asm("fma.rn.f32x2 %0, %1, %2, %3;" : "=l"(acc) : "l"(w), "l"(x), "l"(acc))
#define SPLAT2(d, a)     asm("mov.b64 %0, {%1, %1};" : "=l"(d) : "f"(a))
#define UNPACK2(a, b, d) asm("mov.b64 {%0, %1}, %2;" : "=f"(a), "=f"(b) : "l"(d))

__device__ __forceinline__ uint32_t to_tf32(float v) {
    uint32_t t;
    asm("cvt.rna.tf32.f32 %0, %1;" : "=r"(t) : "f"(v));
    return t;
}

__device__ __forceinline__ void mma_tf32(float& d0, float& d1, float& d2, float& d3,
                                         uint32_t a0, uint32_t a1, uint32_t a2, uint32_t a3,
                                         uint32_t b0, uint32_t b1) {
    asm volatile("mma.sync.aligned.m16n8k8.row.col.f32.tf32.tf32.f32 "
                 "{%0,%1,%2,%3}, {%4,%5,%6,%7}, {%8,%9}, {%0,%1,%2,%3};"
                 : "+f"(d0), "+f"(d1), "+f"(d2), "+f"(d3)
                 : "r"(a0), "r"(a1), "r"(a2), "r"(a3), "r"(b0), "r"(b1));
}

// ============ setup: edge W image, conv W images, epilogue consts, bnsum zero =
__global__ void setup_kernel(const float* __restrict__ rW1, const float* __restrict__ rb1,
                             const float* __restrict__ rW2, const float* __restrict__ rb2,
                             const float* __restrict__ tpW)
{
    const int tid = threadIdx.x;   // 256
    for (int i = tid; i < 48*128; i += 256) {
        int k = i >> 7, j = i & 127;
        float v = 0.0f;
        if (k < 41 && j < 123) {
            int l = j / 41, jj = j - l*41;
            v = rW1[(l*41 + k)*41 + jj];
        }
        g_Wpad[i] = __uint_as_float(to_tf32(v));
    }
    // conv W: g_Wctf[l][col*68 + k] = tf32(tpW[l][k][col] * TPN), pad k>=64 zero
    for (int i = tid; i < NCONVL*64*68; i += 256) {
        int l = i / (64*68), r = i - l*(64*68);
        int col = r / 68, k = r - col*68;
        float v = (k < 64) ? tpW[l*4096 + k*64 + col] * TPN : 0.0f;
        g_Wctf[i] = __uint_as_float(to_tf32(v));
    }
    if (tid < 128) {
        float b1 = 0.0f, w2 = 0.0f;
        if (tid < 123) {
            int l = tid / 41, jj = tid - l*41;
            b1 = rb1[l*41 + jj];
            w2 = rW2[(l*41 + jj)*9] * (Y0C / (float)MNBR);
        }
        g_epib1[tid] = b1;
        g_epiw2[tid] = w2;
    }
    if (tid < 3) g_epir0[tid] = rb2[tid*9] * (Y0C / (float)MNBR);
    for (int i = tid; i < NCONVL*2*FDIM; i += 256) g_bnsum[i] = 0.0f;
}

// ============ edge kernel: persistent, double-buffered, mma.sync tf32 ========
__global__ __launch_bounds__(128, 3) void edge_mma_kernel(const float* __restrict__ nbr_fea)
{
    __shared__ float sA[2][64*52];
    __shared__ float sRed[4][64*3];
    const int tid  = threadIdx.x;
    const int wid  = tid >> 5, lane = tid & 31;
    const int g    = lane >> 2, q = lane & 3;
    const int bid  = blockIdx.x;

    const int wbase = wid * 32;
    uint32_t bf[6][4][2];
    #pragma unroll
    for (int k = 0; k < 6; k++)
        #pragma unroll
        for (int nt = 0; nt < 4; nt++) {
            int col = wbase + nt*8 + g;
            bf[k][nt][0] = __float_as_uint(g_Wpad[(k*8 + q)*128 + col]);
            bf[k][nt][1] = __float_as_uint(g_Wpad[(k*8 + q + 4)*128 + col]);
        }
    float b1a[4], b1b[4], w2a[4], w2b[4];
    int lyA[4], lyB[4];
    #pragma unroll
    for (int nt = 0; nt < 4; nt++) {
        int ja = wbase + nt*8 + q*2, jb = ja + 1;
        b1a[nt] = g_epib1[ja]; b1b[nt] = g_epib1[jb];
        w2a[nt] = g_epiw2[ja]; w2b[nt] = g_epiw2[jb];
        lyA[nt] = (ja < 41) ? 0 : ((ja < 82) ? 1 : 2);
        lyB[nt] = (jb < 41) ? 0 : ((jb < 82) ? 1 : 2);
    }
    const float r0c = g_epir0[0], r1c = g_epir0[1], r2c = g_epir0[2];

    for (int i = tid; i < 64*7; i += 128) {
        int r = i / 7, c = 41 + (i - r*7);
        sA[0][r*52 + c] = 0.0f;
        sA[1][r*52 + c] = 0.0f;
    }
    {
        const float* src = nbr_fea + (size_t)bid * 2624;
        for (int i = tid; i < 2624; i += 128) {
            int r = i / 41, c = i - r*41;
            sA[0][r*52 + c] = __uint_as_float(to_tf32(src[i]));
        }
    }

    int cur = 0;
    for (int t = bid; t < NTILES; t += NBLK) {
        const int tn = t + NBLK;
        const bool have_next = (tn < NTILES);
        __syncthreads();

        float pf[21];
        if (have_next) {
            const float* src = nbr_fea + (size_t)tn * 2624;
            #pragma unroll
            for (int j = 0; j < 20; j++) pf[j] = src[tid + j*128];
            if (tid < 64) pf[20] = src[tid + 2560];
        }

        const float* A = sA[cur];
        #pragma unroll
        for (int m = 0; m < 4; m++) {
            float d[4][4];
            #pragma unroll
            for (int nt = 0; nt < 4; nt++)
                #pragma unroll
                for (int f = 0; f < 4; f++) d[nt][f] = 0.0f;

            const int row0 = m*16 + g, row1 = row0 + 8;
            #pragma unroll
            for (int k = 0; k < 6; k++) {
                uint32_t a0 = __float_as_uint(A[row0*52 + k*8 + q]);
                uint32_t a1 = __float_as_uint(A[row1*52 + k*8 + q]);
                uint32_t a2 = __float_as_uint(A[row0*52 + k*8 + q + 4]);
                uint32_t a3 = __float_as_uint(A[row1*52 + k*8 + q + 4]);
                #pragma unroll
                for (int nt = 0; nt < 4; nt++)
                    mma_tf32(d[nt][0], d[nt][1], d[nt][2], d[nt][3],
                             a0, a1, a2, a3, bf[k][nt][0], bf[k][nt][1]);
            }

            float aA0 = 0.0f, aA1 = 0.0f, aA2 = 0.0f;
            float aB0 = 0.0f, aB1 = 0.0f, aB2 = 0.0f;
            #pragma unroll
            for (int nt = 0; nt < 4; nt++) {
                float v00 = softplus_f(d[nt][0] + b1a[nt]) * w2a[nt];
                float v01 = softplus_f(d[nt][1] + b1b[nt]) * w2b[nt];
                float v10 = softplus_f(d[nt][2] + b1a[nt]) * w2a[nt];
                float v11 = softplus_f(d[nt][3] + b1b[nt]) * w2b[nt];
                if (lyA[nt] == 0) { aA0 += v00; aB0 += v10; }
                else if (lyA[nt] == 1) { aA1 += v00; aB1 += v10; }
                else { aA2 += v00; aB2 += v10; }
                if (lyB[nt] == 0) { aA0 += v01; aB0 += v11; }
                else if (lyB[nt] == 1) { aA1 += v01; aB1 += v11; }
                else { aA2 += v01; aB2 += v11; }
            }
            #pragma unroll
            for (int s = 1; s <= 2; s <<= 1) {
                aA0 += __shfl_xor_sync(0xffffffffu, aA0, s);
                aA1 += __shfl_xor_sync(0xffffffffu, aA1, s);
                aA2 += __shfl_xor_sync(0xffffffffu, aA2, s);
                aB0 += __shfl_xor_sync(0xffffffffu, aB0, s);
                aB1 += __shfl_xor_sync(0xffffffffu, aB1, s);
                aB2 += __shfl_xor_sync(0xffffffffu, aB2, s);
            }
            if (q == 0) {
                sRed[wid][row0*3 + 0] = aA0;
                sRed[wid][row0*3 + 1] = aA1;
                sRed[wid][row0*3 + 2] = aA2;
                sRed[wid][row1*3 + 0] = aB0;
                sRed[wid][row1*3 + 1] = aB1;
                sRed[wid][row1*3 + 2] = aB2;
            }
        }
        __syncthreads();

        const int base = t*64;
        for (int i = tid; i < 64*3; i += 128) {
            int row = i / 3, ly = i - row*3;
            float s = sRed[0][i] + sRed[1][i] + sRed[2][i] + sRed[3][i];
            float r0 = (ly == 0) ? r0c : ((ly == 1) ? r1c : r2c);
            g_w0[ly*NEDGE + base + row] = s + r0;
        }

        if (have_next) {
            float* B = sA[cur ^ 1];
            #pragma unroll
            for (int j = 0; j < 20; j++) {
                int idx = tid + j*128;
                int r = idx / 41, c = idx - r*41;
                B[r*52 + c] = __uint_as_float(to_tf32(pf[j]));
            }
            if (tid < 64) {
                int idx = tid + 2560;
                int r = idx / 41, c = idx - r*41;
                B[r*52 + c] = __uint_as_float(to_tf32(pf[20]));
            }
        }
        cur ^= 1;
    }
}

// =============== embedding: x = atom_fea @ emb_W + emb_b (f32x2) =============
__global__ __launch_bounds__(256) void embed_kernel(
    const float* __restrict__ A, const float* __restrict__ W, const float* __restrict__ bias)
{
    __shared__ float sA[64*93];
    __shared__ __align__(16) float sW[92*64];
    __shared__ float sB[64];
    const int tid = threadIdx.x;
    const int row0 = blockIdx.x * 64;
    for (int i = tid; i < 64*92; i += 256) {
        int r = i / 92, k = i % 92;
        int row = row0 + r;
        sA[r*93 + k] = (row < NATOMS) ? A[row*92 + k] : 0.0f;
    }
    for (int i = tid; i < 92*64; i += 256) sW[i] = W[i];
    if (tid < 64) sB[tid] = bias[tid];
    __syncthreads();
    const int tx = tid & 15, ty = tid >> 4;
    unsigned long long acc[4][2];
    #pragma unroll
    for (int i = 0; i < 4; i++) { acc[i][0] = 0ULL; acc[i][1] = 0ULL; }
    #pragma unroll 4
    for (int k = 0; k < 92; k++) {
        ulonglong2 wv = *(const ulonglong2*)(sW + k*64 + (tx << 2));
        #pragma unroll
        for (int i = 0; i < 4; i++) {
            float a = sA[(ty*4 + i)*93 + k];
            unsigned long long a2; SPLAT2(a2, a);
            FFMA2(acc[i][0], wv.x, a2);
            FFMA2(acc[i][1], wv.y, a2);
        }
    }
    #pragma unroll
    for (int i = 0; i < 4; i++) {
        int row = row0 + ty*4 + i;
        if (row < NATOMS) {
            float4 o;
            UNPACK2(o.x, o.y, acc[i][0]);
            UNPACK2(o.z, o.w, acc[i][1]);
            o.x += sB[tx*4+0]; o.y += sB[tx*4+1];
            o.z += sB[tx*4+2]; o.w += sB[tx*4+3];
            *(float4*)(g_x + row*64 + (tx << 2)) = o;
        }
    }
}

// ====== fused layer kernel: float4 gather + tf32 mma GEMM + stats ============
__global__ __launch_bounds__(256, 4) void conv_fused_kernel(
    const int* __restrict__ nbr_idx, int l)
{
    __shared__ float sS[64*68];
    __shared__ float sWc[64*68];
    __shared__ int   sIdx[64*12];
    __shared__ float sW0[64*12];
    __shared__ float sStat[128];
    const int tid = threadIdx.x;
    const int row0 = blockIdx.x * 64;

    {
        const float4* src = (const float4*)(g_Wctf + l*(64*68));
        float4* dst = (float4*)sWc;
        for (int i = tid; i < 64*68/4; i += 256) dst[i] = src[i];
    }
    if (tid < 128) sStat[tid] = 0.0f;

    {
        const float* w0l = g_w0 + (size_t)l*NEDGE;
        for (int i = tid; i < 64*12; i += 256) {
            int n = row0 + i/12;
            bool v = (n < NATOMS);
            sIdx[i] = v ? nbr_idx[row0*12 + i] : 0;
            sW0[i]  = v ? w0l[row0*12 + i] : 0.0f;
        }
    }
    __syncthreads();

    {
        const int lane = tid & 31, w = tid >> 5;
        const int half = lane >> 4, q4 = lane & 15;
        #pragma unroll
        for (int p = 0; p < 4; p++) {
            const int r = w*8 + p*2 + half;
            float4 acc = make_float4(0.0f, 0.0f, 0.0f, 0.0f);
            #pragma unroll
            for (int m = 0; m < 12; m++) {
                const int nb = sIdx[r*12 + m];
                const float wv = sW0[r*12 + m];
                float4 v = *(const float4*)(g_x + nb*64 + q4*4);
                acc.x = fmaf(wv, v.x, acc.x);
                acc.y = fmaf(wv, v.y, acc.y);
                acc.z = fmaf(wv, v.z, acc.z);
                acc.w = fmaf(wv, v.w, acc.w);
            }
            uint4 t;
            t.x = to_tf32(acc.x); t.y = to_tf32(acc.y);
            t.z = to_tf32(acc.z); t.w = to_tf32(acc.w);
            *(uint4*)(&sS[r*68 + q4*4]) = t;
        }
    }
    __syncthreads();

    const int lane = tid & 31, w = tid >> 5;
    const int mt = w & 3, nh = w >> 2;
    const int g = lane >> 2, q = lane & 3;
    const int ra = mt*16 + g, rb = ra + 8;

    float d[4][4];
    #pragma unroll
    for (int nt = 0; nt < 4; nt++)
        #pragma unroll
        for (int f = 0; f < 4; f++) d[nt][f] = 0.0f;

    #pragma unroll
    for (int k = 0; k < 8; k++) {
        uint32_t a0 = __float_as_uint(sS[ra*68 + k*8 + q]);
        uint32_t a1 = __float_as_uint(sS[rb*68 + k*8 + q]);
        uint32_t a2 = __float_as_uint(sS[ra*68 + k*8 + q + 4]);
        uint32_t a3 = __float_as_uint(sS[rb*68 + k*8 + q + 4]);
        #pragma unroll
        for (int nt = 0; nt < 4; nt++) {
            const int col = nh*32 + nt*8 + g;
            uint32_t b0 = __float_as_uint(sWc[col*68 + k*8 + q]);
            uint32_t b1 = __float_as_uint(sWc[col*68 + k*8 + q + 4]);
            mma_tf32(d[nt][0], d[nt][1], d[nt][2], d[nt][3], a0, a1, a2, a3, b0, b1);
        }
    }

    const int gra = row0 + ra, grb = row0 + rb;
    const bool va = gra < NATOMS, vb = grb < NATOMS;
    float s0[4], s1[4], q0[4], q1[4];
    #pragma unroll
    for (int nt = 0; nt < 4; nt++) {
        const int ja = nh*32 + nt*8 + q*2;
        float o00 = 0.0f, o01 = 0.0f, o10 = 0.0f, o11 = 0.0f;
        if (va) {
            float2 xv = *(const float2*)(g_x + gra*64 + ja);
            o00 = d[nt][0] + xv.x;
            o01 = d[nt][1] + xv.y;
            *(float2*)(g_y + gra*64 + ja) = make_float2(o00, o01);
        }
        if (vb) {
            float2 xv = *(const float2*)(g_x + grb*64 + ja);
            o10 = d[nt][2] + xv.x;
            o11 = d[nt][3] + xv.y;
            *(float2*)(g_y + grb*64 + ja) = make_float2(o10, o11);
        }
        s0[nt] = o00 + o10;
        s1[nt] = o01 + o11;
        q0[nt] = o00*o00 + o10*o10;
        q1[nt] = o01*o01 + o11*o11;
    }
    #pragma unroll
    for (int sft = 4; sft <= 16; sft <<= 1) {
        #pragma unroll
        for (int nt = 0; nt < 4; nt++) {
            s0[nt] += __shfl_xor_sync(0xffffffffu, s0[nt], sft);
            s1[nt] += __shfl_xor_sync(0xffffffffu, s1[nt], sft);
            q0[nt] += __shfl_xor_sync(0xffffffffu, q0[nt], sft);
            q1[nt] += __shfl_xor_sync(0xffffffffu, q1[nt], sft);
        }
    }
    if (g == 0) {
        #pragma unroll
        for (int nt = 0; nt < 4; nt++) {
            const int ja = nh*32 + nt*8 + q*2;
            atomicAdd(&sStat[ja],          s0[nt]);
            atomicAdd(&sStat[ja + 1],      s1[nt]);
            atomicAdd(&sStat[64 + ja],     q0[nt]);
            atomicAdd(&sStat[64 + ja + 1], q1[nt]);
        }
    }
    __syncthreads();
    if (tid < 128) atomicAdd(&g_bnsum[l*128 + tid], sStat[tid]);
}

// =============== BN apply + softplus -> new x (layers 0,1) ===================
__global__ void bn_kernel(const float* __restrict__ gamma, const float* __restrict__ beta, int l)
{
    __shared__ float ssc[64], ssh[64];
    const int tid = threadIdx.x;  // 256
    if (tid < 64) {
        float mu  = g_bnsum[l*128 + tid] * (1.0f/NATOMS);
        float var = g_bnsum[l*128 + 64 + tid] * (1.0f/NATOMS) - mu*mu;
        float sc  = gamma[l*64 + tid] * rsqrtf(var + EPSB);
        ssc[tid] = sc;
        ssh[tid] = beta[l*64 + tid] - mu*sc;
    }
    __syncthreads();
    const int total4 = NATOMS*FDIM/4;
    for (int i = blockIdx.x*256 + tid; i < total4; i += gridDim.x*256) {
        float4 v = ((const float4*)g_y)[i];
        int c = (i & 15) << 2;
        v.x = softplus_f(fmaf(ssc[c+0], v.x, ssh[c+0]));
        v.y = softplus_f(fmaf(ssc[c+1], v.y, ssh[c+1]));
        v.z = softplus_f(fmaf(ssc[c+2], v.z, ssh[c+2]));
        v.w = softplus_f(fmaf(ssc[c+3], v.w, ssh[c+3]));
        ((float4*)g_x)[i] = v;
    }
}

// =============== head: fused BN(layer2) + pooling + MLP ======================
__global__ __launch_bounds__(128) void head_kernel(
    const int* __restrict__ cidx, const float* __restrict__ fcW, const float* __restrict__ fcb,
    const float* __restrict__ outW, const float* __restrict__ outb,
    const float* __restrict__ gamma, const float* __restrict__ beta,
    float* __restrict__ out)
{
    __shared__ float ssc[64], ssh[64];
    __shared__ float spart[128];
    __shared__ float crys[64];
    __shared__ float hred[128];
    const int b = blockIdx.x, tid = threadIdx.x;
    const int f = tid & 63, half = tid >> 6;
    if (tid < 64) {
        float mu  = g_bnsum[2*128 + tid] * (1.0f/NATOMS);
        float var = g_bnsum[2*128 + 64 + tid] * (1.0f/NATOMS) - mu*mu;
        float sc  = gamma[2*64 + tid] * rsqrtf(var + EPSB);
        ssc[tid] = sc;
        ssh[tid] = beta[2*64 + tid] - mu*sc;
    }
    __syncthreads();
    const float sc = ssc[f], sh = ssh[f];
    const int* ci = cidx + b*NPC + half*(NPC/2);
    float a = 0.0f;
    #pragma unroll 4
    for (int i = 0; i < NPC/2; i++)
        a += softplus_f(fmaf(sc, g_y[ci[i]*64 + f], sh));
    spart[tid] = a;
    __syncthreads();
    if (tid < 64) crys[tid] = (spart[tid] + spart[tid + 64]) * (1.0f/NPC);
    __syncthreads();
    float acc = fcb[tid];
    #pragma unroll 8
    for (int k = 0; k < 64; k++) acc = fmaf(crys[k], fcW[k*128 + tid], acc);
    float h = softplus_f(acc);
    out[BQ + b*HFD + tid] = h;
    hred[tid] = h * outW[tid];
    __syncthreads();
    for (int sft = 64; sft > 0; sft >>= 1) {
        if (tid < sft) hred[tid] += hred[tid + sft];
        __syncthreads();
    }
    if (tid == 0) out[b] = hred[0] + outb[0];
}

// ============================================================================
extern "C" void kernel_launch(void* const* d_in, const int* in_sizes, int n_in,
                              void* d_out, int out_size)
{
    const float* atom_fea = (const float*)d_in[0];
    const float* nbr_fea  = (const float*)d_in[1];
    /* d_in[2] = pos (unused: only Y_0 path contributes) */
    const float* emb_W    = (const float*)d_in[3];
    const float* emb_b    = (const float*)d_in[4];
    const float* rW1      = (const float*)d_in[5];
    const float* rb1      = (const float*)d_in[6];
    const float* rW2      = (const float*)d_in[7];
    const float* rb2      = (const float*)d_in[8];
    const float* tpW      = (const float*)d_in[9];
    const float* bn_gamma = (const float*)d_in[10];
    const float* bn_beta  = (const float*)d_in[11];
    const float* fc_W     = (const float*)d_in[12];
    const float* fc_b     = (const float*)d_in[13];
    const float* out_W    = (const float*)d_in[14];
    const float* out_b    = (const float*)d_in[15];
    const int*   nbr_idx  = (const int*)d_in[16];
    const int*   cidx     = (const int*)d_in[17];
    float* out = (float*)d_out;

    setup_kernel<<<1, 256>>>(rW1, rb1, rW2, rb2, tpW);
    embed_kernel<<<(NATOMS + 63)/64, 256>>>(atom_fea, emb_W, emb_b);
    edge_mma_kernel<<<NBLK, 128>>>(nbr_fea);
    for (int l = 0; l < NCONVL; l++) {
        conv_fused_kernel<<<(NATOMS + 63)/64, 256>>>(nbr_idx, l);
        if (l < 2) bn_kernel<<<592, 256>>>(bn_gamma, bn_beta, l);
    }
    head_kernel<<<BQ, 128>>>(cidx, fc_W, fc_b, out_W, out_b, bn_gamma, bn_beta, out);
}

// round 13
// speedup vs baseline: 1.7375x; 1.1286x over previous
#include <cuda_runtime.h>
#include <cuda_fp16.h>
#include <math.h>
#include <stdint.h>

#define NATOMS 100000
#define MNBR   12
#define NEDGE  (NATOMS*MNBR)
#define ORIG   92
#define NBRD   41
#define FDIM   64
#define HFD    128
#define NCONVL 3
#define BQ     500
#define NPC    200
#define Y0C    0.28209479177387814f
#define TPN    0.125f
#define EPSB   1e-5f

#define NTILES (NEDGE/64)     // 18750
#define NBLK   592            // 148 SMs * 4

// ---------------- scratch (no cudaMalloc allowed) ----------------
__device__ float g_x[NATOMS*FDIM];
__device__ float g_y[NATOMS*FDIM];
__device__ float g_w0[3*NEDGE];
__device__ float g_bnsum[NCONVL*2*FDIM];
__device__ uint32_t g_WpadH2[24*128];    // edge W as half2 pairs: [kk][col]
__device__ float g_Wctf[NCONVL*64*68];   // conv W, tf32, exact smem layout [col*68+k]
__device__ float g_epib1[128];
__device__ float g_epiw2[128];
__device__ float g_epir0[3];

__device__ __forceinline__ float softplus_f(float z) {
    float t = fabsf(z);
    float e = __expf(-t);
    return fmaxf(z, 0.0f) + __logf(1.0f + e);
}

#define FFMA2(acc, w, x) asm("fma.rn.f32x2 %0, %1, %2, %3;" : "=l"(acc) : "l"(w), "l"(x), "l"(acc))
#define SPLAT2(d, a)     asm("mov.b64 %0, {%1, %1};" : "=l"(d) : "f"(a))
#define UNPACK2(a, b, d) asm("mov.b64 {%0, %1}, %2;" : "=f"(a), "=f"(b) : "l"(d))

__device__ __forceinline__ uint32_t to_tf32(float v) {
    uint32_t t;
    asm("cvt.rna.tf32.f32 %0, %1;" : "=r"(t) : "f"(v));
    return t;
}

__device__ __forceinline__ void mma_tf32(float& d0, float& d1, float& d2, float& d3,
                                         uint32_t a0, uint32_t a1, uint32_t a2, uint32_t a3,
                                         uint32_t b0, uint32_t b1) {
    asm volatile("mma.sync.aligned.m16n8k8.row.col.f32.tf32.tf32.f32 "
                 "{%0,%1,%2,%3}, {%4,%5,%6,%7}, {%8,%9}, {%0,%1,%2,%3};"
                 : "+f"(d0), "+f"(d1), "+f"(d2), "+f"(d3)
                 : "r"(a0), "r"(a1), "r"(a2), "r"(a3), "r"(b0), "r"(b1));
}

__device__ __forceinline__ void mma_f16(float& d0, float& d1, float& d2, float& d3,
                                        uint32_t a0, uint32_t a1, uint32_t a2, uint32_t a3,
                                        uint32_t b0, uint32_t b1) {
    asm volatile("mma.sync.aligned.m16n8k16.row.col.f32.f16.f16.f32 "
                 "{%0,%1,%2,%3}, {%4,%5,%6,%7}, {%8,%9}, {%0,%1,%2,%3};"
                 : "+f"(d0), "+f"(d1), "+f"(d2), "+f"(d3)
                 : "r"(a0), "r"(a1), "r"(a2), "r"(a3), "r"(b0), "r"(b1));
}

// ============ setup: edge W half2 image, conv W images, consts, bnsum zero ===
__global__ void setup_kernel(const float* __restrict__ rW1, const float* __restrict__ rb1,
                             const float* __restrict__ rW2, const float* __restrict__ rb2,
                             const float* __restrict__ tpW)
{
    const int tid = threadIdx.x;   // 256
    // edge W as half2 K-pairs: g_WpadH2[kk*128 + j] = (W[2kk][j], W[2kk+1][j])
    for (int i = tid; i < 24*128; i += 256) {
        int kk = i >> 7, j = i & 127;
        float v0 = 0.0f, v1 = 0.0f;
        if (j < 123) {
            int l = j / 41, jj = j - l*41;
            int k0 = 2*kk, k1 = 2*kk + 1;
            if (k0 < 41) v0 = rW1[(l*41 + k0)*41 + jj];
            if (k1 < 41) v1 = rW1[(l*41 + k1)*41 + jj];
        }
        __half2 h = __floats2half2_rn(v0, v1);
        g_WpadH2[i] = *(uint32_t*)&h;
    }
    for (int i = tid; i < NCONVL*64*68; i += 256) {
        int l = i / (64*68), r = i - l*(64*68);
        int col = r / 68, k = r - col*68;
        float v = (k < 64) ? tpW[l*4096 + k*64 + col] * TPN : 0.0f;
        g_Wctf[i] = __uint_as_float(to_tf32(v));
    }
    if (tid < 128) {
        float b1 = 0.0f, w2 = 0.0f;
        if (tid < 123) {
            int l = tid / 41, jj = tid - l*41;
            b1 = rb1[l*41 + jj];
            w2 = rW2[(l*41 + jj)*9] * (Y0C / (float)MNBR);
        }
        g_epib1[tid] = b1;
        g_epiw2[tid] = w2;
    }
    if (tid < 3) g_epir0[tid] = rb2[tid*9] * (Y0C / (float)MNBR);
    for (int i = tid; i < NCONVL*2*FDIM; i += 256) g_bnsum[i] = 0.0f;
}

// ============ edge kernel: persistent, double-buffered, mma.sync f16 =========
// A rows stored as half2 pairs, row stride 28 u32 (bank-exact: 28g+q distinct).
__global__ __launch_bounds__(128, 4) void edge_mma_kernel(const float* __restrict__ nbr_fea)
{
    __shared__ uint32_t sA[2][64*28];
    __shared__ float sRed[4][64*3];
    const int tid  = threadIdx.x;
    const int wid  = tid >> 5, lane = tid & 31;
    const int g    = lane >> 2, q = lane & 3;
    const int bid  = blockIdx.x;

    // ---- one-time: B fragments (half2 pairs) + epilogue constants ----
    const int wbase = wid * 32;
    uint32_t bf[3][4][2];
    #pragma unroll
    for (int k = 0; k < 3; k++)
        #pragma unroll
        for (int nt = 0; nt < 4; nt++) {
            int col = wbase + nt*8 + g;
            bf[k][nt][0] = g_WpadH2[(k*8 + q)*128 + col];
            bf[k][nt][1] = g_WpadH2[(k*8 + q + 4)*128 + col];
        }
    float b1a[4], b1b[4], w2a[4], w2b[4];
    int lyA[4], lyB[4];
    #pragma unroll
    for (int nt = 0; nt < 4; nt++) {
        int ja = wbase + nt*8 + q*2, jb = ja + 1;
        b1a[nt] = g_epib1[ja]; b1b[nt] = g_epib1[jb];
        w2a[nt] = g_epiw2[ja]; w2b[nt] = g_epiw2[jb];
        lyA[nt] = (ja < 41) ? 0 : ((ja < 82) ? 1 : 2);
        lyB[nt] = (jb < 41) ? 0 : ((jb < 82) ? 1 : 2);
    }
    const float r0c = g_epir0[0], r1c = g_epir0[1], r2c = g_epir0[2];

    // ---- zero K-pad pairs (u32 20..23 per row; half 40 is overwritten each tile,
    //      its upper half (k=41) and pairs 21..23 stay zero forever) ----
    for (int i = tid; i < 64*4; i += 128) {
        int r = i >> 2, c = 20 + (i & 3);
        sA[0][r*28 + c] = 0u;
        sA[1][r*28 + c] = 0u;
    }
    // ---- prologue: stage first tile into buf 0 (16-bit stores) ----
    {
        const float* src = nbr_fea + (size_t)bid * 2624;
        __half* dst = (__half*)sA[0];
        for (int i = tid; i < 2624; i += 128) {
            int r = i / 41, c = i - r*41;
            dst[r*56 + c] = __float2half_rn(src[i]);
        }
    }

    int cur = 0;
    for (int t = bid; t < NTILES; t += NBLK) {
        const int tn = t + NBLK;
        const bool have_next = (tn < NTILES);
        __syncthreads();                       // buf[cur] staged

        // ---- prefetch next tile's A into registers ----
        float pf[21];
        if (have_next) {
            const float* src = nbr_fea + (size_t)tn * 2624;
            #pragma unroll
            for (int j = 0; j < 20; j++) pf[j] = src[tid + j*128];
            if (tid < 64) pf[20] = src[tid + 2560];
        }

        // ---- f16 MMA + epilogue on buf[cur] ----
        const uint32_t* A = sA[cur];
        #pragma unroll
        for (int m = 0; m < 4; m++) {
            float d[4][4];
            #pragma unroll
            for (int nt = 0; nt < 4; nt++)
                #pragma unroll
                for (int f = 0; f < 4; f++) d[nt][f] = 0.0f;

            const int row0 = m*16 + g, row1 = row0 + 8;
            #pragma unroll
            for (int k = 0; k < 3; k++) {
                uint32_t a0 = A[row0*28 + k*8 + q];
                uint32_t a1 = A[row1*28 + k*8 + q];
                uint32_t a2 = A[row0*28 + k*8 + q + 4];
                uint32_t a3 = A[row1*28 + k*8 + q + 4];
                #pragma unroll
                for (int nt = 0; nt < 4; nt++)
                    mma_f16(d[nt][0], d[nt][1], d[nt][2], d[nt][3],
                            a0, a1, a2, a3, bf[k][nt][0], bf[k][nt][1]);
            }

            float aA0 = 0.0f, aA1 = 0.0f, aA2 = 0.0f;
            float aB0 = 0.0f, aB1 = 0.0f, aB2 = 0.0f;
            #pragma unroll
            for (int nt = 0; nt < 4; nt++) {
                float v00 = softplus_f(d[nt][0] + b1a[nt]) * w2a[nt];
                float v01 = softplus_f(d[nt][1] + b1b[nt]) * w2b[nt];
                float v10 = softplus_f(d[nt][2] + b1a[nt]) * w2a[nt];
                float v11 = softplus_f(d[nt][3] + b1b[nt]) * w2b[nt];
                if (lyA[nt] == 0) { aA0 += v00; aB0 += v10; }
                else if (lyA[nt] == 1) { aA1 += v00; aB1 += v10; }
                else { aA2 += v00; aB2 += v10; }
                if (lyB[nt] == 0) { aA0 += v01; aB0 += v11; }
                else if (lyB[nt] == 1) { aA1 += v01; aB1 += v11; }
                else { aA2 += v01; aB2 += v11; }
            }
            #pragma unroll
            for (int s = 1; s <= 2; s <<= 1) {
                aA0 += __shfl_xor_sync(0xffffffffu, aA0, s);
                aA1 += __shfl_xor_sync(0xffffffffu, aA1, s);
                aA2 += __shfl_xor_sync(0xffffffffu, aA2, s);
                aB0 += __shfl_xor_sync(0xffffffffu, aB0, s);
                aB1 += __shfl_xor_sync(0xffffffffu, aB1, s);
                aB2 += __shfl_xor_sync(0xffffffffu, aB2, s);
            }
            if (q == 0) {
                sRed[wid][row0*3 + 0] = aA0;
                sRed[wid][row0*3 + 1] = aA1;
                sRed[wid][row0*3 + 2] = aA2;
                sRed[wid][row1*3 + 0] = aB0;
                sRed[wid][row1*3 + 1] = aB1;
                sRed[wid][row1*3 + 2] = aB2;
            }
        }
        __syncthreads();                       // sRed done; buf[cur] consumed

        // ---- combine + write w0 for tile t ----
        const int base = t*64;
        for (int i = tid; i < 64*3; i += 128) {
            int row = i / 3, ly = i - row*3;
            float s = sRed[0][i] + sRed[1][i] + sRed[2][i] + sRed[3][i];
            float r0 = (ly == 0) ? r0c : ((ly == 1) ? r1c : r2c);
            g_w0[ly*NEDGE + base + row] = s + r0;
        }

        // ---- store prefetched tile into other buffer ----
        if (have_next) {
            __half* B = (__half*)sA[cur ^ 1];
            #pragma unroll
            for (int j = 0; j < 20; j++) {
                int idx = tid + j*128;
                int r = idx / 41, c = idx - r*41;
                B[r*56 + c] = __float2half_rn(pf[j]);
            }
            if (tid < 64) {
                int idx = tid + 2560;
                int r = idx / 41, c = idx - r*41;
                B[r*56 + c] = __float2half_rn(pf[20]);
            }
        }
        cur ^= 1;
    }
}

// =============== embedding: x = atom_fea @ emb_W + emb_b (f32x2) =============
__global__ __launch_bounds__(256) void embed_kernel(
    const float* __restrict__ A, const float* __restrict__ W, const float* __restrict__ bias)
{
    __shared__ float sA[64*93];
    __shared__ __align__(16) float sW[92*64];
    __shared__ float sB[64];
    const int tid = threadIdx.x;
    const int row0 = blockIdx.x * 64;
    for (int i = tid; i < 64*92; i += 256) {
        int r = i / 92, k = i % 92;
        int row = row0 + r;
        sA[r*93 + k] = (row < NATOMS) ? A[row*92 + k] : 0.0f;
    }
    for (int i = tid; i < 92*64; i += 256) sW[i] = W[i];
    if (tid < 64) sB[tid] = bias[tid];
    __syncthreads();
    const int tx = tid & 15, ty = tid >> 4;
    unsigned long long acc[4][2];
    #pragma unroll
    for (int i = 0; i < 4; i++) { acc[i][0] = 0ULL; acc[i][1] = 0ULL; }
    #pragma unroll 4
    for (int k = 0; k < 92; k++) {
        ulonglong2 wv = *(const ulonglong2*)(sW + k*64 + (tx << 2));
        #pragma unroll
        for (int i = 0; i < 4; i++) {
            float a = sA[(ty*4 + i)*93 + k];
            unsigned long long a2; SPLAT2(a2, a);
            FFMA2(acc[i][0], wv.x, a2);
            FFMA2(acc[i][1], wv.y, a2);
        }
    }
    #pragma unroll
    for (int i = 0; i < 4; i++) {
        int row = row0 + ty*4 + i;
        if (row < NATOMS) {
            float4 o;
            UNPACK2(o.x, o.y, acc[i][0]);
            UNPACK2(o.z, o.w, acc[i][1]);
            o.x += sB[tx*4+0]; o.y += sB[tx*4+1];
            o.z += sB[tx*4+2]; o.w += sB[tx*4+3];
            *(float4*)(g_x + row*64 + (tx << 2)) = o;
        }
    }
}

// ====== fused layer kernel: float4 gather + tf32 mma GEMM + stats ============
__global__ __launch_bounds__(256, 4) void conv_fused_kernel(
    const int* __restrict__ nbr_idx, int l)
{
    __shared__ float sS[64*68];
    __shared__ float sWc[64*68];
    __shared__ int   sIdx[64*12];
    __shared__ float sW0[64*12];
    __shared__ float sStat[128];
    const int tid = threadIdx.x;
    const int row0 = blockIdx.x * 64;

    {
        const float4* src = (const float4*)(g_Wctf + l*(64*68));
        float4* dst = (float4*)sWc;
        for (int i = tid; i < 64*68/4; i += 256) dst[i] = src[i];
    }
    if (tid < 128) sStat[tid] = 0.0f;

    {
        const float* w0l = g_w0 + (size_t)l*NEDGE;
        for (int i = tid; i < 64*12; i += 256) {
            int n = row0 + i/12;
            bool v = (n < NATOMS);
            sIdx[i] = v ? nbr_idx[row0*12 + i] : 0;
            sW0[i]  = v ? w0l[row0*12 + i] : 0.0f;
        }
    }
    __syncthreads();

    {
        const int lane = tid & 31, w = tid >> 5;
        const int half = lane >> 4, q4 = lane & 15;
        #pragma unroll
        for (int p = 0; p < 4; p++) {
            const int r = w*8 + p*2 + half;
            float4 acc = make_float4(0.0f, 0.0f, 0.0f, 0.0f);
            #pragma unroll
            for (int m = 0; m < 12; m++) {
                const int nb = sIdx[r*12 + m];
                const float wv = sW0[r*12 + m];
                float4 v = *(const float4*)(g_x + nb*64 + q4*4);
                acc.x = fmaf(wv, v.x, acc.x);
                acc.y = fmaf(wv, v.y, acc.y);
                acc.z = fmaf(wv, v.z, acc.z);
                acc.w = fmaf(wv, v.w, acc.w);
            }
            uint4 t;
            t.x = to_tf32(acc.x); t.y = to_tf32(acc.y);
            t.z = to_tf32(acc.z); t.w = to_tf32(acc.w);
            *(uint4*)(&sS[r*68 + q4*4]) = t;
        }
    }
    __syncthreads();

    const int lane = tid & 31, w = tid >> 5;
    const int mt = w & 3, nh = w >> 2;
    const int g = lane >> 2, q = lane & 3;
    const int ra = mt*16 + g, rb = ra + 8;

    float d[4][4];
    #pragma unroll
    for (int nt = 0; nt < 4; nt++)
        #pragma unroll
        for (int f = 0; f < 4; f++) d[nt][f] = 0.0f;

    #pragma unroll
    for (int k = 0; k < 8; k++) {
        uint32_t a0 = __float_as_uint(sS[ra*68 + k*8 + q]);
        uint32_t a1 = __float_as_uint(sS[rb*68 + k*8 + q]);
        uint32_t a2 = __float_as_uint(sS[ra*68 + k*8 + q + 4]);
        uint32_t a3 = __float_as_uint(sS[rb*68 + k*8 + q + 4]);
        #pragma unroll
        for (int nt = 0; nt < 4; nt++) {
            const int col = nh*32 + nt*8 + g;
            uint32_t b0 = __float_as_uint(sWc[col*68 + k*8 + q]);
            uint32_t b1 = __float_as_uint(sWc[col*68 + k*8 + q + 4]);
            mma_tf32(d[nt][0], d[nt][1], d[nt][2], d[nt][3], a0, a1, a2, a3, b0, b1);
        }
    }

    const int gra = row0 + ra, grb = row0 + rb;
    const bool va = gra < NATOMS, vb = grb < NATOMS;
    float s0[4], s1[4], q0[4], q1[4];
    #pragma unroll
    for (int nt = 0; nt < 4; nt++) {
        const int ja = nh*32 + nt*8 + q*2;
        float o00 = 0.0f, o01 = 0.0f, o10 = 0.0f, o11 = 0.0f;
        if (va) {
            float2 xv = *(const float2*)(g_x + gra*64 + ja);
            o00 = d[nt][0] + xv.x;
            o01 = d[nt][1] + xv.y;
            *(float2*)(g_y + gra*64 + ja) = make_float2(o00, o01);
        }
        if (vb) {
            float2 xv = *(const float2*)(g_x + grb*64 + ja);
            o10 = d[nt][2] + xv.x;
            o11 = d[nt][3] + xv.y;
            *(float2*)(g_y + grb*64 + ja) = make_float2(o10, o11);
        }
        s0[nt] = o00 + o10;
        s1[nt] = o01 + o11;
        q0[nt] = o00*o00 + o10*o10;
        q1[nt] = o01*o01 + o11*o11;
    }
    #pragma unroll
    for (int sft = 4; sft <= 16; sft <<= 1) {
        #pragma unroll
        for (int nt = 0; nt < 4; nt++) {
            s0[nt] += __shfl_xor_sync(0xffffffffu, s0[nt], sft);
            s1[nt] += __shfl_xor_sync(0xffffffffu, s1[nt], sft);
            q0[nt] += __shfl_xor_sync(0xffffffffu, q0[nt], sft);
            q1[nt] += __shfl_xor_sync(0xffffffffu, q1[nt], sft);
        }
    }
    if (g == 0) {
        #pragma unroll
        for (int nt = 0; nt < 4; nt++) {
            const int ja = nh*32 + nt*8 + q*2;
            atomicAdd(&sStat[ja],          s0[nt]);
            atomicAdd(&sStat[ja + 1],      s1[nt]);
            atomicAdd(&sStat[64 + ja],     q0[nt]);
            atomicAdd(&sStat[64 + ja + 1], q1[nt]);
        }
    }
    __syncthreads();
    if (tid < 128) atomicAdd(&g_bnsum[l*128 + tid], sStat[tid]);
}

// =============== BN apply + softplus -> new x (layers 0,1) ===================
__global__ void bn_kernel(const float* __restrict__ gamma, const float* __restrict__ beta, int l)
{
    __shared__ float ssc[64], ssh[64];
    const int tid = threadIdx.x;  // 256
    if (tid < 64) {
        float mu  = g_bnsum[l*128 + tid] * (1.0f/NATOMS);
        float var = g_bnsum[l*128 + 64 + tid] * (1.0f/NATOMS) - mu*mu;
        float sc  = gamma[l*64 + tid] * rsqrtf(var + EPSB);
        ssc[tid] = sc;
        ssh[tid] = beta[l*64 + tid] - mu*sc;
    }
    __syncthreads();
    const int total4 = NATOMS*FDIM/4;
    for (int i = blockIdx.x*256 + tid; i < total4; i += gridDim.x*256) {
        float4 v = ((const float4*)g_y)[i];
        int c = (i & 15) << 2;
        v.x = softplus_f(fmaf(ssc[c+0], v.x, ssh[c+0]));
        v.y = softplus_f(fmaf(ssc[c+1], v.y, ssh[c+1]));
        v.z = softplus_f(fmaf(ssc[c+2], v.z, ssh[c+2]));
        v.w = softplus_f(fmaf(ssc[c+3], v.w, ssh[c+3]));
        ((float4*)g_x)[i] = v;
    }
}

// =============== head: fused BN(layer2) + pooling + MLP ======================
__global__ __launch_bounds__(128) void head_kernel(
    const int* __restrict__ cidx, const float* __restrict__ fcW, const float* __restrict__ fcb,
    const float* __restrict__ outW, const float* __restrict__ outb,
    const float* __restrict__ gamma, const float* __restrict__ beta,
    float* __restrict__ out)
{
    __shared__ float ssc[64], ssh[64];
    __shared__ float spart[128];
    __shared__ float crys[64];
    __shared__ float hred[128];
    const int b = blockIdx.x, tid = threadIdx.x;
    const int f = tid & 63, half = tid >> 6;
    if (tid < 64) {
        float mu  = g_bnsum[2*128 + tid] * (1.0f/NATOMS);
        float var = g_bnsum[2*128 + 64 + tid] * (1.0f/NATOMS) - mu*mu;
        float sc  = gamma[2*64 + tid] * rsqrtf(var + EPSB);
        ssc[tid] = sc;
        ssh[tid] = beta[2*64 + tid] - mu*sc;
    }
    __syncthreads();
    const float sc = ssc[f], sh = ssh[f];
    const int* ci = cidx + b*NPC + half*(NPC/2);
    float a = 0.0f;
    #pragma unroll 4
    for (int i = 0; i < NPC/2; i++)
        a += softplus_f(fmaf(sc, g_y[ci[i]*64 + f], sh));
    spart[tid] = a;
    __syncthreads();
    if (tid < 64) crys[tid] = (spart[tid] + spart[tid + 64]) * (1.0f/NPC);
    __syncthreads();
    float acc = fcb[tid];
    #pragma unroll 8
    for (int k = 0; k < 64; k++) acc = fmaf(crys[k], fcW[k*128 + tid], acc);
    float h = softplus_f(acc);
    out[BQ + b*HFD + tid] = h;
    hred[tid] = h * outW[tid];
    __syncthreads();
    for (int sft = 64; sft > 0; sft >>= 1) {
        if (tid < sft) hred[tid] += hred[tid + sft];
        __syncthreads();
    }
    if (tid == 0) out[b] = hred[0] + outb[0];
}

// ============================================================================
extern "C" void kernel_launch(void* const* d_in, const int* in_sizes, int n_in,
                              void* d_out, int out_size)
{
    const float* atom_fea = (const float*)d_in[0];
    const float* nbr_fea  = (const float*)d_in[1];
    /* d_in[2] = pos (unused: only Y_0 path contributes) */
    const float* emb_W    = (const float*)d_in[3];
    const float* emb_b    = (const float*)d_in[4];
    const float* rW1      = (const float*)d_in[5];
    const float* rb1      = (const float*)d_in[6];
    const float* rW2      = (const float*)d_in[7];
    const float* rb2      = (const float*)d_in[8];
    const float* tpW      = (const float*)d_in[9];
    const float* bn_gamma = (const float*)d_in[10];
    const float* bn_beta  = (const float*)d_in[11];
    const float* fc_W     = (const float*)d_in[12];
    const float* fc_b     = (const float*)d_in[13];
    const float* out_W    = (const float*)d_in[14];
    const float* out_b    = (const float*)d_in[15];
    const int*   nbr_idx  = (const int*)d_in[16];
    const int*   cidx     = (const int*)d_in[17];
    float* out = (float*)d_out;

    setup_kernel<<<1, 256>>>(rW1, rb1, rW2, rb2, tpW);
    embed_kernel<<<(NATOMS + 63)/64, 256>>>(atom_fea, emb_W, emb_b);
    edge_mma_kernel<<<NBLK, 128>>>(nbr_fea);
    for (int l = 0; l < NCONVL; l++) {
        conv_fused_kernel<<<(NATOMS + 63)/64, 256>>>(nbr_idx, l);
        if (l < 2) bn_kernel<<<592, 256>>>(bn_gamma, bn_beta, l);
    }
    head_kernel<<<BQ, 128>>>(cidx, fc_W, fc_b, out_W, out_b, bn_gamma, bn_beta, out);
}

// round 14
// speedup vs baseline: 1.8490x; 1.0642x over previous
#include <cuda_runtime.h>
#include <cuda_fp16.h>
#include <math.h>
#include <stdint.h>

#define NATOMS 100000
#define MNBR   12
#define NEDGE  (NATOMS*MNBR)
#define ORIG   92
#define NBRD   41
#define FDIM   64
#define HFD    128
#define NCONVL 3
#define BQ     500
#define NPC    200
#define Y0C    0.28209479177387814f
#define TPN    0.125f
#define EPSB   1e-5f

#define NTILES (NEDGE/64)     // 18750
#define NBLK   592            // 148 SMs * 4

// ---------------- scratch (no cudaMalloc allowed) ----------------
__device__ __half g_xh[NATOMS*FDIM];     // atom features, fp16 (one 128B line/row)
__device__ float g_y[NATOMS*FDIM];
__device__ float g_w0[3*NEDGE];
__device__ float g_bnsum[NCONVL*2*FDIM];
__device__ uint32_t g_WpadH2[24*128];    // edge W as half2 pairs: [kk][col]
__device__ float g_Wctf[NCONVL*64*68];   // conv W, tf32, exact smem layout [col*68+k]
__device__ float g_epib1[128];
__device__ float g_epiw2[128];
__device__ float g_epir0[3];

__device__ __forceinline__ float softplus_f(float z) {
    float t = fabsf(z);
    float e = __expf(-t);
    return fmaxf(z, 0.0f) + __logf(1.0f + e);
}

#define FFMA2(acc, w, x) asm("fma.rn.f32x2 %0, %1, %2, %3;" : "=l"(acc) : "l"(w), "l"(x), "l"(acc))
#define SPLAT2(d, a)     asm("mov.b64 %0, {%1, %1};" : "=l"(d) : "f"(a))
#define UNPACK2(a, b, d) asm("mov.b64 {%0, %1}, %2;" : "=f"(a), "=f"(b) : "l"(d))

__device__ __forceinline__ uint32_t to_tf32(float v) {
    uint32_t t;
    asm("cvt.rna.tf32.f32 %0, %1;" : "=r"(t) : "f"(v));
    return t;
}

__device__ __forceinline__ void mma_tf32(float& d0, float& d1, float& d2, float& d3,
                                         uint32_t a0, uint32_t a1, uint32_t a2, uint32_t a3,
                                         uint32_t b0, uint32_t b1) {
    asm volatile("mma.sync.aligned.m16n8k8.row.col.f32.tf32.tf32.f32 "
                 "{%0,%1,%2,%3}, {%4,%5,%6,%7}, {%8,%9}, {%0,%1,%2,%3};"
                 : "+f"(d0), "+f"(d1), "+f"(d2), "+f"(d3)
                 : "r"(a0), "r"(a1), "r"(a2), "r"(a3), "r"(b0), "r"(b1));
}

__device__ __forceinline__ void mma_f16(float& d0, float& d1, float& d2, float& d3,
                                        uint32_t a0, uint32_t a1, uint32_t a2, uint32_t a3,
                                        uint32_t b0, uint32_t b1) {
    asm volatile("mma.sync.aligned.m16n8k16.row.col.f32.f16.f16.f32 "
                 "{%0,%1,%2,%3}, {%4,%5,%6,%7}, {%8,%9}, {%0,%1,%2,%3};"
                 : "+f"(d0), "+f"(d1), "+f"(d2), "+f"(d3)
                 : "r"(a0), "r"(a1), "r"(a2), "r"(a3), "r"(b0), "r"(b1));
}

// ============ setup: edge W half2 image, conv W images, consts, bnsum zero ===
__global__ void setup_kernel(const float* __restrict__ rW1, const float* __restrict__ rb1,
                             const float* __restrict__ rW2, const float* __restrict__ rb2,
                             const float* __restrict__ tpW)
{
    const int tid = threadIdx.x;   // 256
    for (int i = tid; i < 24*128; i += 256) {
        int kk = i >> 7, j = i & 127;
        float v0 = 0.0f, v1 = 0.0f;
        if (j < 123) {
            int l = j / 41, jj = j - l*41;
            int k0 = 2*kk, k1 = 2*kk + 1;
            if (k0 < 41) v0 = rW1[(l*41 + k0)*41 + jj];
            if (k1 < 41) v1 = rW1[(l*41 + k1)*41 + jj];
        }
        __half2 h = __floats2half2_rn(v0, v1);
        g_WpadH2[i] = *(uint32_t*)&h;
    }
    for (int i = tid; i < NCONVL*64*68; i += 256) {
        int l = i / (64*68), r = i - l*(64*68);
        int col = r / 68, k = r - col*68;
        float v = (k < 64) ? tpW[l*4096 + k*64 + col] * TPN : 0.0f;
        g_Wctf[i] = __uint_as_float(to_tf32(v));
    }
    if (tid < 128) {
        float b1 = 0.0f, w2 = 0.0f;
        if (tid < 123) {
            int l = tid / 41, jj = tid - l*41;
            b1 = rb1[l*41 + jj];
            w2 = rW2[(l*41 + jj)*9] * (Y0C / (float)MNBR);
        }
        g_epib1[tid] = b1;
        g_epiw2[tid] = w2;
    }
    if (tid < 3) g_epir0[tid] = rb2[tid*9] * (Y0C / (float)MNBR);
    for (int i = tid; i < NCONVL*2*FDIM; i += 256) g_bnsum[i] = 0.0f;
}

// ============ edge kernel: persistent, double-buffered, mma.sync f16 =========
__global__ __launch_bounds__(128, 4) void edge_mma_kernel(const float* __restrict__ nbr_fea)
{
    __shared__ uint32_t sA[2][64*28];
    __shared__ float sRed[4][64*3];
    const int tid  = threadIdx.x;
    const int wid  = tid >> 5, lane = tid & 31;
    const int g    = lane >> 2, q = lane & 3;
    const int bid  = blockIdx.x;

    const int wbase = wid * 32;
    uint32_t bf[3][4][2];
    #pragma unroll
    for (int k = 0; k < 3; k++)
        #pragma unroll
        for (int nt = 0; nt < 4; nt++) {
            int col = wbase + nt*8 + g;
            bf[k][nt][0] = g_WpadH2[(k*8 + q)*128 + col];
            bf[k][nt][1] = g_WpadH2[(k*8 + q + 4)*128 + col];
        }
    float b1a[4], b1b[4], w2a[4], w2b[4];
    int lyA[4], lyB[4];
    #pragma unroll
    for (int nt = 0; nt < 4; nt++) {
        int ja = wbase + nt*8 + q*2, jb = ja + 1;
        b1a[nt] = g_epib1[ja]; b1b[nt] = g_epib1[jb];
        w2a[nt] = g_epiw2[ja]; w2b[nt] = g_epiw2[jb];
        lyA[nt] = (ja < 41) ? 0 : ((ja < 82) ? 1 : 2);
        lyB[nt] = (jb < 41) ? 0 : ((jb < 82) ? 1 : 2);
    }
    const float r0c = g_epir0[0], r1c = g_epir0[1], r2c = g_epir0[2];

    for (int i = tid; i < 64*4; i += 128) {
        int r = i >> 2, c = 20 + (i & 3);
        sA[0][r*28 + c] = 0u;
        sA[1][r*28 + c] = 0u;
    }
    {
        const float* src = nbr_fea + (size_t)bid * 2624;
        __half* dst = (__half*)sA[0];
        for (int i = tid; i < 2624; i += 128) {
            int r = i / 41, c = i - r*41;
            dst[r*56 + c] = __float2half_rn(src[i]);
        }
    }

    int cur = 0;
    for (int t = bid; t < NTILES; t += NBLK) {
        const int tn = t + NBLK;
        const bool have_next = (tn < NTILES);
        __syncthreads();

        float pf[21];
        if (have_next) {
            const float* src = nbr_fea + (size_t)tn * 2624;
            #pragma unroll
            for (int j = 0; j < 20; j++) pf[j] = src[tid + j*128];
            if (tid < 64) pf[20] = src[tid + 2560];
        }

        const uint32_t* A = sA[cur];
        #pragma unroll
        for (int m = 0; m < 4; m++) {
            float d[4][4];
            #pragma unroll
            for (int nt = 0; nt < 4; nt++)
                #pragma unroll
                for (int f = 0; f < 4; f++) d[nt][f] = 0.0f;

            const int row0 = m*16 + g, row1 = row0 + 8;
            #pragma unroll
            for (int k = 0; k < 3; k++) {
                uint32_t a0 = A[row0*28 + k*8 + q];
                uint32_t a1 = A[row1*28 + k*8 + q];
                uint32_t a2 = A[row0*28 + k*8 + q + 4];
                uint32_t a3 = A[row1*28 + k*8 + q + 4];
                #pragma unroll
                for (int nt = 0; nt < 4; nt++)
                    mma_f16(d[nt][0], d[nt][1], d[nt][2], d[nt][3],
                            a0, a1, a2, a3, bf[k][nt][0], bf[k][nt][1]);
            }

            float aA0 = 0.0f, aA1 = 0.0f, aA2 = 0.0f;
            float aB0 = 0.0f, aB1 = 0.0f, aB2 = 0.0f;
            #pragma unroll
            for (int nt = 0; nt < 4; nt++) {
                float v00 = softplus_f(d[nt][0] + b1a[nt]) * w2a[nt];
                float v01 = softplus_f(d[nt][1] + b1b[nt]) * w2b[nt];
                float v10 = softplus_f(d[nt][2] + b1a[nt]) * w2a[nt];
                float v11 = softplus_f(d[nt][3] + b1b[nt]) * w2b[nt];
                if (lyA[nt] == 0) { aA0 += v00; aB0 += v10; }
                else if (lyA[nt] == 1) { aA1 += v00; aB1 += v10; }
                else { aA2 += v00; aB2 += v10; }
                if (lyB[nt] == 0) { aA0 += v01; aB0 += v11; }
                else if (lyB[nt] == 1) { aA1 += v01; aB1 += v11; }
                else { aA2 += v01; aB2 += v11; }
            }
            #pragma unroll
            for (int s = 1; s <= 2; s <<= 1) {
                aA0 += __shfl_xor_sync(0xffffffffu, aA0, s);
                aA1 += __shfl_xor_sync(0xffffffffu, aA1, s);
                aA2 += __shfl_xor_sync(0xffffffffu, aA2, s);
                aB0 += __shfl_xor_sync(0xffffffffu, aB0, s);
                aB1 += __shfl_xor_sync(0xffffffffu, aB1, s);
                aB2 += __shfl_xor_sync(0xffffffffu, aB2, s);
            }
            if (q == 0) {
                sRed[wid][row0*3 + 0] = aA0;
                sRed[wid][row0*3 + 1] = aA1;
                sRed[wid][row0*3 + 2] = aA2;
                sRed[wid][row1*3 + 0] = aB0;
                sRed[wid][row1*3 + 1] = aB1;
                sRed[wid][row1*3 + 2] = aB2;
            }
        }
        __syncthreads();

        const int base = t*64;
        for (int i = tid; i < 64*3; i += 128) {
            int row = i / 3, ly = i - row*3;
            float s = sRed[0][i] + sRed[1][i] + sRed[2][i] + sRed[3][i];
            float r0 = (ly == 0) ? r0c : ((ly == 1) ? r1c : r2c);
            g_w0[ly*NEDGE + base + row] = s + r0;
        }

        if (have_next) {
            __half* B = (__half*)sA[cur ^ 1];
            #pragma unroll
            for (int j = 0; j < 20; j++) {
                int idx = tid + j*128;
                int r = idx / 41, c = idx - r*41;
                B[r*56 + c] = __float2half_rn(pf[j]);
            }
            if (tid < 64) {
                int idx = tid + 2560;
                int r = idx / 41, c = idx - r*41;
                B[r*56 + c] = __float2half_rn(pf[20]);
            }
        }
        cur ^= 1;
    }
}

// =============== embedding: x = atom_fea @ emb_W + emb_b -> fp16 ============
__global__ __launch_bounds__(256) void embed_kernel(
    const float* __restrict__ A, const float* __restrict__ W, const float* __restrict__ bias)
{
    __shared__ float sA[64*93];
    __shared__ __align__(16) float sW[92*64];
    __shared__ float sB[64];
    const int tid = threadIdx.x;
    const int row0 = blockIdx.x * 64;
    for (int i = tid; i < 64*92; i += 256) {
        int r = i / 92, k = i % 92;
        int row = row0 + r;
        sA[r*93 + k] = (row < NATOMS) ? A[row*92 + k] : 0.0f;
    }
    for (int i = tid; i < 92*64; i += 256) sW[i] = W[i];
    if (tid < 64) sB[tid] = bias[tid];
    __syncthreads();
    const int tx = tid & 15, ty = tid >> 4;
    unsigned long long acc[4][2];
    #pragma unroll
    for (int i = 0; i < 4; i++) { acc[i][0] = 0ULL; acc[i][1] = 0ULL; }
    #pragma unroll 4
    for (int k = 0; k < 92; k++) {
        ulonglong2 wv = *(const ulonglong2*)(sW + k*64 + (tx << 2));
        #pragma unroll
        for (int i = 0; i < 4; i++) {
            float a = sA[(ty*4 + i)*93 + k];
            unsigned long long a2; SPLAT2(a2, a);
            FFMA2(acc[i][0], wv.x, a2);
            FFMA2(acc[i][1], wv.y, a2);
        }
    }
    #pragma unroll
    for (int i = 0; i < 4; i++) {
        int row = row0 + ty*4 + i;
        if (row < NATOMS) {
            float4 o;
            UNPACK2(o.x, o.y, acc[i][0]);
            UNPACK2(o.z, o.w, acc[i][1]);
            o.x += sB[tx*4+0]; o.y += sB[tx*4+1];
            o.z += sB[tx*4+2]; o.w += sB[tx*4+3];
            __half2 h0 = __floats2half2_rn(o.x, o.y);
            __half2 h1 = __floats2half2_rn(o.z, o.w);
            uint2 st;
            st.x = *(uint32_t*)&h0;
            st.y = *(uint32_t*)&h1;
            *(uint2*)(g_xh + row*64 + (tx << 2)) = st;
        }
    }
}

// ====== fused layer kernel: fp16 gather + tf32 mma GEMM + stats ==============
__global__ __launch_bounds__(256, 4) void conv_fused_kernel(
    const int* __restrict__ nbr_idx, int l)
{
    __shared__ float sS[64*68];
    __shared__ float sWc[64*68];
    __shared__ int   sIdx[64*12];
    __shared__ float sW0[64*12];
    __shared__ float sStat[128];
    const int tid = threadIdx.x;
    const int row0 = blockIdx.x * 64;

    {
        const float4* src = (const float4*)(g_Wctf + l*(64*68));
        float4* dst = (float4*)sWc;
        for (int i = tid; i < 64*68/4; i += 256) dst[i] = src[i];
    }
    if (tid < 128) sStat[tid] = 0.0f;

    {
        const float* w0l = g_w0 + (size_t)l*NEDGE;
        for (int i = tid; i < 64*12; i += 256) {
            int n = row0 + i/12;
            bool v = (n < NATOMS);
            sIdx[i] = v ? nbr_idx[row0*12 + i] : 0;
            sW0[i]  = v ? w0l[row0*12 + i] : 0.0f;
        }
    }
    __syncthreads();

    // ---- gather phase: fp16 rows (128B/row, one line), 16 lanes per row ----
    {
        const int lane = tid & 31, w = tid >> 5;
        const int half = lane >> 4, q4 = lane & 15;
        #pragma unroll
        for (int p = 0; p < 4; p++) {
            const int r = w*8 + p*2 + half;
            float4 acc = make_float4(0.0f, 0.0f, 0.0f, 0.0f);
            #pragma unroll
            for (int m = 0; m < 12; m++) {
                const int nb = sIdx[r*12 + m];
                const float wv = sW0[r*12 + m];
                uint2 v = *(const uint2*)(g_xh + nb*64 + (q4 << 2));
                float2 f0 = __half22float2(*(__half2*)&v.x);
                float2 f1 = __half22float2(*(__half2*)&v.y);
                acc.x = fmaf(wv, f0.x, acc.x);
                acc.y = fmaf(wv, f0.y, acc.y);
                acc.z = fmaf(wv, f1.x, acc.z);
                acc.w = fmaf(wv, f1.y, acc.w);
            }
            uint4 t;
            t.x = to_tf32(acc.x); t.y = to_tf32(acc.y);
            t.z = to_tf32(acc.z); t.w = to_tf32(acc.w);
            *(uint4*)(&sS[r*68 + (q4 << 2)]) = t;
        }
    }
    __syncthreads();

    const int lane = tid & 31, w = tid >> 5;
    const int mt = w & 3, nh = w >> 2;
    const int g = lane >> 2, q = lane & 3;
    const int ra = mt*16 + g, rb = ra + 8;

    float d[4][4];
    #pragma unroll
    for (int nt = 0; nt < 4; nt++)
        #pragma unroll
        for (int f = 0; f < 4; f++) d[nt][f] = 0.0f;

    #pragma unroll
    for (int k = 0; k < 8; k++) {
        uint32_t a0 = __float_as_uint(sS[ra*68 + k*8 + q]);
        uint32_t a1 = __float_as_uint(sS[rb*68 + k*8 + q]);
        uint32_t a2 = __float_as_uint(sS[ra*68 + k*8 + q + 4]);
        uint32_t a3 = __float_as_uint(sS[rb*68 + k*8 + q + 4]);
        #pragma unroll
        for (int nt = 0; nt < 4; nt++) {
            const int col = nh*32 + nt*8 + g;
            uint32_t b0 = __float_as_uint(sWc[col*68 + k*8 + q]);
            uint32_t b1 = __float_as_uint(sWc[col*68 + k*8 + q + 4]);
            mma_tf32(d[nt][0], d[nt][1], d[nt][2], d[nt][3], a0, a1, a2, a3, b0, b1);
        }
    }

    const int gra = row0 + ra, grb = row0 + rb;
    const bool va = gra < NATOMS, vb = grb < NATOMS;
    float s0[4], s1[4], q0[4], q1[4];
    #pragma unroll
    for (int nt = 0; nt < 4; nt++) {
        const int ja = nh*32 + nt*8 + q*2;
        float o00 = 0.0f, o01 = 0.0f, o10 = 0.0f, o11 = 0.0f;
        if (va) {
            float2 xv = __half22float2(*(const __half2*)(g_xh + gra*64 + ja));
            o00 = d[nt][0] + xv.x;
            o01 = d[nt][1] + xv.y;
            *(float2*)(g_y + gra*64 + ja) = make_float2(o00, o01);
        }
        if (vb) {
            float2 xv = __half22float2(*(const __half2*)(g_xh + grb*64 + ja));
            o10 = d[nt][2] + xv.x;
            o11 = d[nt][3] + xv.y;
            *(float2*)(g_y + grb*64 + ja) = make_float2(o10, o11);
        }
        s0[nt] = o00 + o10;
        s1[nt] = o01 + o11;
        q0[nt] = o00*o00 + o10*o10;
        q1[nt] = o01*o01 + o11*o11;
    }
    #pragma unroll
    for (int sft = 4; sft <= 16; sft <<= 1) {
        #pragma unroll
        for (int nt = 0; nt < 4; nt++) {
            s0[nt] += __shfl_xor_sync(0xffffffffu, s0[nt], sft);
            s1[nt] += __shfl_xor_sync(0xffffffffu, s1[nt], sft);
            q0[nt] += __shfl_xor_sync(0xffffffffu, q0[nt], sft);
            q1[nt] += __shfl_xor_sync(0xffffffffu, q1[nt], sft);
        }
    }
    if (g == 0) {
        #pragma unroll
        for (int nt = 0; nt < 4; nt++) {
            const int ja = nh*32 + nt*8 + q*2;
            atomicAdd(&sStat[ja],          s0[nt]);
            atomicAdd(&sStat[ja + 1],      s1[nt]);
            atomicAdd(&sStat[64 + ja],     q0[nt]);
            atomicAdd(&sStat[64 + ja + 1], q1[nt]);
        }
    }
    __syncthreads();
    if (tid < 128) atomicAdd(&g_bnsum[l*128 + tid], sStat[tid]);
}

// =============== BN apply + softplus -> new fp16 x (layers 0,1) ==============
__global__ void bn_kernel(const float* __restrict__ gamma, const float* __restrict__ beta, int l)
{
    __shared__ float ssc[64], ssh[64];
    const int tid = threadIdx.x;  // 256
    if (tid < 64) {
        float mu  = g_bnsum[l*128 + tid] * (1.0f/NATOMS);
        float var = g_bnsum[l*128 + 64 + tid] * (1.0f/NATOMS) - mu*mu;
        float sc  = gamma[l*64 + tid] * rsqrtf(var + EPSB);
        ssc[tid] = sc;
        ssh[tid] = beta[l*64 + tid] - mu*sc;
    }
    __syncthreads();
    const int total4 = NATOMS*FDIM/4;
    for (int i = blockIdx.x*256 + tid; i < total4; i += gridDim.x*256) {
        float4 v = ((const float4*)g_y)[i];
        int c = (i & 15) << 2;
        v.x = softplus_f(fmaf(ssc[c+0], v.x, ssh[c+0]));
        v.y = softplus_f(fmaf(ssc[c+1], v.y, ssh[c+1]));
        v.z = softplus_f(fmaf(ssc[c+2], v.z, ssh[c+2]));
        v.w = softplus_f(fmaf(ssc[c+3], v.w, ssh[c+3]));
        __half2 h0 = __floats2half2_rn(v.x, v.y);
        __half2 h1 = __floats2half2_rn(v.z, v.w);
        uint2 st;
        st.x = *(uint32_t*)&h0;
        st.y = *(uint32_t*)&h1;
        ((uint2*)g_xh)[i] = st;
    }
}

// =============== head: fused BN(layer2) + pooling + MLP ======================
__global__ __launch_bounds__(128) void head_kernel(
    const int* __restrict__ cidx, const float* __restrict__ fcW, const float* __restrict__ fcb,
    const float* __restrict__ outW, const float* __restrict__ outb,
    const float* __restrict__ gamma, const float* __restrict__ beta,
    float* __restrict__ out)
{
    __shared__ float ssc[64], ssh[64];
    __shared__ float spart[128];
    __shared__ float crys[64];
    __shared__ float hred[128];
    const int b = blockIdx.x, tid = threadIdx.x;
    const int f = tid & 63, half = tid >> 6;
    if (tid < 64) {
        float mu  = g_bnsum[2*128 + tid] * (1.0f/NATOMS);
        float var = g_bnsum[2*128 + 64 + tid] * (1.0f/NATOMS) - mu*mu;
        float sc  = gamma[2*64 + tid] * rsqrtf(var + EPSB);
        ssc[tid] = sc;
        ssh[tid] = beta[2*64 + tid] - mu*sc;
    }
    __syncthreads();
    const float sc = ssc[f], sh = ssh[f];
    const int* ci = cidx + b*NPC + half*(NPC/2);
    float a = 0.0f;
    #pragma unroll 4
    for (int i = 0; i < NPC/2; i++)
        a += softplus_f(fmaf(sc, g_y[ci[i]*64 + f], sh));
    spart[tid] = a;
    __syncthreads();
    if (tid < 64) crys[tid] = (spart[tid] + spart[tid + 64]) * (1.0f/NPC);
    __syncthreads();
    float acc = fcb[tid];
    #pragma unroll 8
    for (int k = 0; k < 64; k++) acc = fmaf(crys[k], fcW[k*128 + tid], acc);
    float h = softplus_f(acc);
    out[BQ + b*HFD + tid] = h;
    hred[tid] = h * outW[tid];
    __syncthreads();
    for (int sft = 64; sft > 0; sft >>= 1) {
        if (tid < sft) hred[tid] += hred[tid + sft];
        __syncthreads();
    }
    if (tid == 0) out[b] = hred[0] + outb[0];
}

// ============================================================================
extern "C" void kernel_launch(void* const* d_in, const int* in_sizes, int n_in,
                              void* d_out, int out_size)
{
    const float* atom_fea = (const float*)d_in[0];
    const float* nbr_fea  = (const float*)d_in[1];
    /* d_in[2] = pos (unused: only Y_0 path contributes) */
    const float* emb_W    = (const float*)d_in[3];
    const float* emb_b    = (const float*)d_in[4];
    const float* rW1      = (const float*)d_in[5];
    const float* rb1      = (const float*)d_in[6];
    const float* rW2      = (const float*)d_in[7];
    const float* rb2      = (const float*)d_in[8];
    const float* tpW      = (const float*)d_in[9];
    const float* bn_gamma = (const float*)d_in[10];
    const float* bn_beta  = (const float*)d_in[11];
    const float* fc_W     = (const float*)d_in[12];
    const float* fc_b     = (const float*)d_in[13];
    const float* out_W    = (const float*)d_in[14];
    const float* out_b    = (const float*)d_in[15];
    const int*   nbr_idx  = (const int*)d_in[16];
    const int*   cidx     = (const int*)d_in[17];
    float* out = (float*)d_out;

    setup_kernel<<<1, 256>>>(rW1, rb1, rW2, rb2, tpW);
    embed_kernel<<<(NATOMS + 63)/64, 256>>>(atom_fea, emb_W, emb_b);
    edge_mma_kernel<<<NBLK, 128>>>(nbr_fea);
    for (int l = 0; l < NCONVL; l++) {
        conv_fused_kernel<<<(NATOMS + 63)/64, 256>>>(nbr_idx, l);
        if (l < 2) bn_kernel<<<592, 256>>>(bn_gamma, bn_beta, l);
    }
    head_kernel<<<BQ, 128>>>(cidx, fc_W, fc_b, out_W, out_b, bn_gamma, bn_beta, out);
}

// round 15
// speedup vs baseline: 1.9438x; 1.0513x over previous
#include <cuda_runtime.h>
#include <cuda_fp16.h>
#include <math.h>
#include <stdint.h>

#define NATOMS 100000
#define MNBR   12
#define NEDGE  (NATOMS*MNBR)
#define ORIG   92
#define NBRD   41
#define FDIM   64
#define HFD    128
#define NCONVL 3
#define BQ     500
#define NPC    200
#define Y0C    0.28209479177387814f
#define TPN    0.125f
#define EPSB   1e-5f

#define NTILES (NEDGE/64)     // 18750
#define NBLK   592            // 148 SMs * 4 (edge kernel)
#define NCT    1563           // conv tiles = ceil(NATOMS/64)
#define CBLK   592            // persistent conv blocks (one wave at occ 4)

// ---------------- scratch (no cudaMalloc allowed) ----------------
__device__ __half g_xh[NATOMS*FDIM];     // atom features, fp16 (one 128B line/row)
__device__ float g_y[NATOMS*FDIM];
__device__ float g_w0[3*NEDGE];
__device__ float g_bnsum[NCONVL*2*FDIM];
__device__ uint32_t g_WpadH2[24*128];    // edge W as half2 pairs: [kk][col]
__device__ uint32_t g_Wcth[NCONVL*64*36]; // conv W half2 pairs, [col*36 + pair]
__device__ float g_epib1[128];
__device__ float g_epiw2[128];
__device__ float g_epir0[3];

__device__ __forceinline__ float softplus_f(float z) {
    float t = fabsf(z);
    float e = __expf(-t);
    return fmaxf(z, 0.0f) + __logf(1.0f + e);
}

#define FFMA2(acc, w, x) asm("fma.rn.f32x2 %0, %1, %2, %3;" : "=l"(acc) : "l"(w), "l"(x), "l"(acc))
#define SPLAT2(d, a)     asm("mov.b64 %0, {%1, %1};" : "=l"(d) : "f"(a))
#define UNPACK2(a, b, d) asm("mov.b64 {%0, %1}, %2;" : "=f"(a), "=f"(b) : "l"(d))

__device__ __forceinline__ void mma_f16(float& d0, float& d1, float& d2, float& d3,
                                        uint32_t a0, uint32_t a1, uint32_t a2, uint32_t a3,
                                        uint32_t b0, uint32_t b1) {
    asm volatile("mma.sync.aligned.m16n8k16.row.col.f32.f16.f16.f32 "
                 "{%0,%1,%2,%3}, {%4,%5,%6,%7}, {%8,%9}, {%0,%1,%2,%3};"
                 : "+f"(d0), "+f"(d1), "+f"(d2), "+f"(d3)
                 : "r"(a0), "r"(a1), "r"(a2), "r"(a3), "r"(b0), "r"(b1));
}

// ============ setup: edge W half2 image, conv W half2 images, consts =========
__global__ void setup_kernel(const float* __restrict__ rW1, const float* __restrict__ rb1,
                             const float* __restrict__ rW2, const float* __restrict__ rb2,
                             const float* __restrict__ tpW)
{
    const int tid = threadIdx.x;   // 256
    for (int i = tid; i < 24*128; i += 256) {
        int kk = i >> 7, j = i & 127;
        float v0 = 0.0f, v1 = 0.0f;
        if (j < 123) {
            int l = j / 41, jj = j - l*41;
            int k0 = 2*kk, k1 = 2*kk + 1;
            if (k0 < 41) v0 = rW1[(l*41 + k0)*41 + jj];
            if (k1 < 41) v1 = rW1[(l*41 + k1)*41 + jj];
        }
        __half2 h = __floats2half2_rn(v0, v1);
        g_WpadH2[i] = *(uint32_t*)&h;
    }
    // conv W half2 pairs: g_Wcth[l][col*36 + p] = half2(tpW[l][2p][col], tpW[l][2p+1][col]) * TPN
    for (int i = tid; i < NCONVL*64*36; i += 256) {
        int l = i / (64*36), r = i - l*(64*36);
        int col = r / 36, p = r - col*36;
        float v0 = 0.0f, v1 = 0.0f;
        if (p < 32) {
            v0 = tpW[l*4096 + (2*p)*64 + col] * TPN;
            v1 = tpW[l*4096 + (2*p + 1)*64 + col] * TPN;
        }
        __half2 h = __floats2half2_rn(v0, v1);
        g_Wcth[i] = *(uint32_t*)&h;
    }
    if (tid < 128) {
        float b1 = 0.0f, w2 = 0.0f;
        if (tid < 123) {
            int l = tid / 41, jj = tid - l*41;
            b1 = rb1[l*41 + jj];
            w2 = rW2[(l*41 + jj)*9] * (Y0C / (float)MNBR);
        }
        g_epib1[tid] = b1;
        g_epiw2[tid] = w2;
    }
    if (tid < 3) g_epir0[tid] = rb2[tid*9] * (Y0C / (float)MNBR);
    for (int i = tid; i < NCONVL*2*FDIM; i += 256) g_bnsum[i] = 0.0f;
}

// ============ edge kernel: persistent, double-buffered, mma.sync f16 =========
__global__ __launch_bounds__(128, 4) void edge_mma_kernel(const float* __restrict__ nbr_fea)
{
    __shared__ uint32_t sA[2][64*28];
    __shared__ float sRed[4][64*3];
    const int tid  = threadIdx.x;
    const int wid  = tid >> 5, lane = tid & 31;
    const int g    = lane >> 2, q = lane & 3;
    const int bid  = blockIdx.x;

    const int wbase = wid * 32;
    uint32_t bf[3][4][2];
    #pragma unroll
    for (int k = 0; k < 3; k++)
        #pragma unroll
        for (int nt = 0; nt < 4; nt++) {
            int col = wbase + nt*8 + g;
            bf[k][nt][0] = g_WpadH2[(k*8 + q)*128 + col];
            bf[k][nt][1] = g_WpadH2[(k*8 + q + 4)*128 + col];
        }
    float b1a[4], b1b[4], w2a[4], w2b[4];
    int lyA[4], lyB[4];
    #pragma unroll
    for (int nt = 0; nt < 4; nt++) {
        int ja = wbase + nt*8 + q*2, jb = ja + 1;
        b1a[nt] = g_epib1[ja]; b1b[nt] = g_epib1[jb];
        w2a[nt] = g_epiw2[ja]; w2b[nt] = g_epiw2[jb];
        lyA[nt] = (ja < 41) ? 0 : ((ja < 82) ? 1 : 2);
        lyB[nt] = (jb < 41) ? 0 : ((jb < 82) ? 1 : 2);
    }
    const float r0c = g_epir0[0], r1c = g_epir0[1], r2c = g_epir0[2];

    for (int i = tid; i < 64*4; i += 128) {
        int r = i >> 2, c = 20 + (i & 3);
        sA[0][r*28 + c] = 0u;
        sA[1][r*28 + c] = 0u;
    }
    {
        const float* src = nbr_fea + (size_t)bid * 2624;
        __half* dst = (__half*)sA[0];
        for (int i = tid; i < 2624; i += 128) {
            int r = i / 41, c = i - r*41;
            dst[r*56 + c] = __float2half_rn(src[i]);
        }
    }

    int cur = 0;
    for (int t = bid; t < NTILES; t += NBLK) {
        const int tn = t + NBLK;
        const bool have_next = (tn < NTILES);
        __syncthreads();

        float pf[21];
        if (have_next) {
            const float* src = nbr_fea + (size_t)tn * 2624;
            #pragma unroll
            for (int j = 0; j < 20; j++) pf[j] = src[tid + j*128];
            if (tid < 64) pf[20] = src[tid + 2560];
        }

        const uint32_t* A = sA[cur];
        #pragma unroll
        for (int m = 0; m < 4; m++) {
            float d[4][4];
            #pragma unroll
            for (int nt = 0; nt < 4; nt++)
                #pragma unroll
                for (int f = 0; f < 4; f++) d[nt][f] = 0.0f;

            const int row0 = m*16 + g, row1 = row0 + 8;
            #pragma unroll
            for (int k = 0; k < 3; k++) {
                uint32_t a0 = A[row0*28 + k*8 + q];
                uint32_t a1 = A[row1*28 + k*8 + q];
                uint32_t a2 = A[row0*28 + k*8 + q + 4];
                uint32_t a3 = A[row1*28 + k*8 + q + 4];
                #pragma unroll
                for (int nt = 0; nt < 4; nt++)
                    mma_f16(d[nt][0], d[nt][1], d[nt][2], d[nt][3],
                            a0, a1, a2, a3, bf[k][nt][0], bf[k][nt][1]);
            }

            float aA0 = 0.0f, aA1 = 0.0f, aA2 = 0.0f;
            float aB0 = 0.0f, aB1 = 0.0f, aB2 = 0.0f;
            #pragma unroll
            for (int nt = 0; nt < 4; nt++) {
                float v00 = softplus_f(d[nt][0] + b1a[nt]) * w2a[nt];
                float v01 = softplus_f(d[nt][1] + b1b[nt]) * w2b[nt];
                float v10 = softplus_f(d[nt][2] + b1a[nt]) * w2a[nt];
                float v11 = softplus_f(d[nt][3] + b1b[nt]) * w2b[nt];
                if (lyA[nt] == 0) { aA0 += v00; aB0 += v10; }
                else if (lyA[nt] == 1) { aA1 += v00; aB1 += v10; }
                else { aA2 += v00; aB2 += v10; }
                if (lyB[nt] == 0) { aA0 += v01; aB0 += v11; }
                else if (lyB[nt] == 1) { aA1 += v01; aB1 += v11; }
                else { aA2 += v01; aB2 += v11; }
            }
            #pragma unroll
            for (int s = 1; s <= 2; s <<= 1) {
                aA0 += __shfl_xor_sync(0xffffffffu, aA0, s);
                aA1 += __shfl_xor_sync(0xffffffffu, aA1, s);
                aA2 += __shfl_xor_sync(0xffffffffu, aA2, s);
                aB0 += __shfl_xor_sync(0xffffffffu, aB0, s);
                aB1 += __shfl_xor_sync(0xffffffffu, aB1, s);
                aB2 += __shfl_xor_sync(0xffffffffu, aB2, s);
            }
            if (q == 0) {
                sRed[wid][row0*3 + 0] = aA0;
                sRed[wid][row0*3 + 1] = aA1;
                sRed[wid][row0*3 + 2] = aA2;
                sRed[wid][row1*3 + 0] = aB0;
                sRed[wid][row1*3 + 1] = aB1;
                sRed[wid][row1*3 + 2] = aB2;
            }
        }
        __syncthreads();

        const int base = t*64;
        for (int i = tid; i < 64*3; i += 128) {
            int row = i / 3, ly = i - row*3;
            float s = sRed[0][i] + sRed[1][i] + sRed[2][i] + sRed[3][i];
            float r0 = (ly == 0) ? r0c : ((ly == 1) ? r1c : r2c);
            g_w0[ly*NEDGE + base + row] = s + r0;
        }

        if (have_next) {
            __half* B = (__half*)sA[cur ^ 1];
            #pragma unroll
            for (int j = 0; j < 20; j++) {
                int idx = tid + j*128;
                int r = idx / 41, c = idx - r*41;
                B[r*56 + c] = __float2half_rn(pf[j]);
            }
            if (tid < 64) {
                int idx = tid + 2560;
                int r = idx / 41, c = idx - r*41;
                B[r*56 + c] = __float2half_rn(pf[20]);
            }
        }
        cur ^= 1;
    }
}

// =============== embedding: x = atom_fea @ emb_W + emb_b -> fp16 ============
__global__ __launch_bounds__(256) void embed_kernel(
    const float* __restrict__ A, const float* __restrict__ W, const float* __restrict__ bias)
{
    __shared__ float sA[64*93];
    __shared__ __align__(16) float sW[92*64];
    __shared__ float sB[64];
    const int tid = threadIdx.x;
    const int row0 = blockIdx.x * 64;
    for (int i = tid; i < 64*92; i += 256) {
        int r = i / 92, k = i % 92;
        int row = row0 + r;
        sA[r*93 + k] = (row < NATOMS) ? A[row*92 + k] : 0.0f;
    }
    for (int i = tid; i < 92*64; i += 256) sW[i] = W[i];
    if (tid < 64) sB[tid] = bias[tid];
    __syncthreads();
    const int tx = tid & 15, ty = tid >> 4;
    unsigned long long acc[4][2];
    #pragma unroll
    for (int i = 0; i < 4; i++) { acc[i][0] = 0ULL; acc[i][1] = 0ULL; }
    #pragma unroll 4
    for (int k = 0; k < 92; k++) {
        ulonglong2 wv = *(const ulonglong2*)(sW + k*64 + (tx << 2));
        #pragma unroll
        for (int i = 0; i < 4; i++) {
            float a = sA[(ty*4 + i)*93 + k];
            unsigned long long a2; SPLAT2(a2, a);
            FFMA2(acc[i][0], wv.x, a2);
            FFMA2(acc[i][1], wv.y, a2);
        }
    }
    #pragma unroll
    for (int i = 0; i < 4; i++) {
        int row = row0 + ty*4 + i;
        if (row < NATOMS) {
            float4 o;
            UNPACK2(o.x, o.y, acc[i][0]);
            UNPACK2(o.z, o.w, acc[i][1]);
            o.x += sB[tx*4+0]; o.y += sB[tx*4+1];
            o.z += sB[tx*4+2]; o.w += sB[tx*4+3];
            __half2 h0 = __floats2half2_rn(o.x, o.y);
            __half2 h1 = __floats2half2_rn(o.z, o.w);
            uint2 st;
            st.x = *(uint32_t*)&h0;
            st.y = *(uint32_t*)&h1;
            *(uint2*)(g_xh + row*64 + (tx << 2)) = st;
        }
    }
}

// ====== persistent fused layer kernel: fp16 gather + f16 mma GEMM + stats ====
__global__ __launch_bounds__(256, 4) void conv_fused_kernel(
    const int* __restrict__ nbr_idx, int l)
{
    __shared__ uint32_t sS[64*36];      // half2 pairs, row stride 36
    __shared__ uint32_t sWh[64*36];     // W half2 pairs, col stride 36
    __shared__ int   sIdx[64*12];
    __shared__ float sW0[64*12];
    __shared__ float sStat[128];
    const int tid = threadIdx.x;

    // ---- stage W pairs once per block ----
    {
        const uint4* src = (const uint4*)(g_Wcth + l*(64*36));
        uint4* dst = (uint4*)sWh;
        for (int i = tid; i < 64*36/4; i += 256) dst[i] = src[i];
    }
    if (tid < 128) sStat[tid] = 0.0f;

    const int lane = tid & 31, w = tid >> 5;
    const int halfl = lane >> 4, q4 = lane & 15;
    const int mt = w & 3, nh = w >> 2;
    const int g = lane >> 2, q = lane & 3;

    const float* w0l = g_w0 + (size_t)l*NEDGE;

    for (int t = blockIdx.x; t < NCT; t += CBLK) {
        const int row0 = t * 64;
        __syncthreads();   // sIdx/sW0/sS from previous tile fully consumed

        // ---- stage idx + w0 tiles ----
        for (int i = tid; i < 64*12; i += 256) {
            int n = row0 + i/12;
            bool v = (n < NATOMS);
            sIdx[i] = v ? nbr_idx[row0*12 + i] : 0;
            sW0[i]  = v ? w0l[row0*12 + i] : 0.0f;
        }
        __syncthreads();

        // ---- gather: fp16 rows, 16 lanes per row, output half2 pairs ----
        #pragma unroll
        for (int p = 0; p < 4; p++) {
            const int r = w*8 + p*2 + halfl;
            float4 acc = make_float4(0.0f, 0.0f, 0.0f, 0.0f);
            #pragma unroll
            for (int m = 0; m < 12; m++) {
                const int nb = sIdx[r*12 + m];
                const float wv = sW0[r*12 + m];
                uint2 v = *(const uint2*)(g_xh + nb*64 + (q4 << 2));
                float2 f0 = __half22float2(*(__half2*)&v.x);
                float2 f1 = __half22float2(*(__half2*)&v.y);
                acc.x = fmaf(wv, f0.x, acc.x);
                acc.y = fmaf(wv, f0.y, acc.y);
                acc.z = fmaf(wv, f1.x, acc.z);
                acc.w = fmaf(wv, f1.y, acc.w);
            }
            __half2 h0 = __floats2half2_rn(acc.x, acc.y);
            __half2 h1 = __floats2half2_rn(acc.z, acc.w);
            uint2 st;
            st.x = *(uint32_t*)&h0;
            st.y = *(uint32_t*)&h1;
            *(uint2*)(&sS[r*36 + 2*q4]) = st;
        }
        __syncthreads();

        // ---- f16 mma GEMM: warp (mt, nh): rows mt*16..+15, cols nh*32..+31 ----
        const int ra = mt*16 + g, rb = ra + 8;
        float d[4][4];
        #pragma unroll
        for (int nt = 0; nt < 4; nt++)
            #pragma unroll
            for (int f = 0; f < 4; f++) d[nt][f] = 0.0f;

        #pragma unroll
        for (int k = 0; k < 4; k++) {
            uint32_t a0 = sS[ra*36 + k*8 + q];
            uint32_t a1 = sS[rb*36 + k*8 + q];
            uint32_t a2 = sS[ra*36 + k*8 + q + 4];
            uint32_t a3 = sS[rb*36 + k*8 + q + 4];
            #pragma unroll
            for (int nt = 0; nt < 4; nt++) {
                const int col = nh*32 + nt*8 + g;
                uint32_t b0 = sWh[col*36 + k*8 + q];
                uint32_t b1 = sWh[col*36 + k*8 + q + 4];
                mma_f16(d[nt][0], d[nt][1], d[nt][2], d[nt][3], a0, a1, a2, a3, b0, b1);
            }
        }

        // ---- epilogue: residual + y write + column stats ----
        const int gra = row0 + ra, grb = row0 + rb;
        const bool va = gra < NATOMS, vb = grb < NATOMS;
        float s0[4], s1[4], q0[4], q1[4];
        #pragma unroll
        for (int nt = 0; nt < 4; nt++) {
            const int ja = nh*32 + nt*8 + q*2;
            float o00 = 0.0f, o01 = 0.0f, o10 = 0.0f, o11 = 0.0f;
            if (va) {
                float2 xv = __half22float2(*(const __half2*)(g_xh + gra*64 + ja));
                o00 = d[nt][0] + xv.x;
                o01 = d[nt][1] + xv.y;
                *(float2*)(g_y + gra*64 + ja) = make_float2(o00, o01);
            }
            if (vb) {
                float2 xv = __half22float2(*(const __half2*)(g_xh + grb*64 + ja));
                o10 = d[nt][2] + xv.x;
                o11 = d[nt][3] + xv.y;
                *(float2*)(g_y + grb*64 + ja) = make_float2(o10, o11);
            }
            s0[nt] = o00 + o10;
            s1[nt] = o01 + o11;
            q0[nt] = o00*o00 + o10*o10;
            q1[nt] = o01*o01 + o11*o11;
        }
        #pragma unroll
        for (int sft = 4; sft <= 16; sft <<= 1) {
            #pragma unroll
            for (int nt = 0; nt < 4; nt++) {
                s0[nt] += __shfl_xor_sync(0xffffffffu, s0[nt], sft);
                s1[nt] += __shfl_xor_sync(0xffffffffu, s1[nt], sft);
                q0[nt] += __shfl_xor_sync(0xffffffffu, q0[nt], sft);
                q1[nt] += __shfl_xor_sync(0xffffffffu, q1[nt], sft);
            }
        }
        if (g == 0) {
            #pragma unroll
            for (int nt = 0; nt < 4; nt++) {
                const int ja = nh*32 + nt*8 + q*2;
                atomicAdd(&sStat[ja],          s0[nt]);
                atomicAdd(&sStat[ja + 1],      s1[nt]);
                atomicAdd(&sStat[64 + ja],     q0[nt]);
                atomicAdd(&sStat[64 + ja + 1], q1[nt]);
            }
        }
    }

    // ---- single global stats flush per block ----
    __syncthreads();
    if (tid < 128) atomicAdd(&g_bnsum[l*128 + tid], sStat[tid]);
}

// =============== BN apply + softplus -> new fp16 x (layers 0,1) ==============
__global__ void bn_kernel(const float* __restrict__ gamma, const float* __restrict__ beta, int l)
{
    __shared__ float ssc[64], ssh[64];
    const int tid = threadIdx.x;  // 256
    if (tid < 64) {
        float mu  = g_bnsum[l*128 + tid] * (1.0f/NATOMS);
        float var = g_bnsum[l*128 + 64 + tid] * (1.0f/NATOMS) - mu*mu;
        float sc  = gamma[l*64 + tid] * rsqrtf(var + EPSB);
        ssc[tid] = sc;
        ssh[tid] = beta[l*64 + tid] - mu*sc;
    }
    __syncthreads();
    const int total4 = NATOMS*FDIM/4;
    for (int i = blockIdx.x*256 + tid; i < total4; i += gridDim.x*256) {
        float4 v = ((const float4*)g_y)[i];
        int c = (i & 15) << 2;
        v.x = softplus_f(fmaf(ssc[c+0], v.x, ssh[c+0]));
        v.y = softplus_f(fmaf(ssc[c+1], v.y, ssh[c+1]));
        v.z = softplus_f(fmaf(ssc[c+2], v.z, ssh[c+2]));
        v.w = softplus_f(fmaf(ssc[c+3], v.w, ssh[c+3]));
        __half2 h0 = __floats2half2_rn(v.x, v.y);
        __half2 h1 = __floats2half2_rn(v.z, v.w);
        uint2 st;
        st.x = *(uint32_t*)&h0;
        st.y = *(uint32_t*)&h1;
        ((uint2*)g_xh)[i] = st;
    }
}

// =============== head: fused BN(layer2) + pooling + MLP ======================
__global__ __launch_bounds__(128) void head_kernel(
    const int* __restrict__ cidx, const float* __restrict__ fcW, const float* __restrict__ fcb,
    const float* __restrict__ outW, const float* __restrict__ outb,
    const float* __restrict__ gamma, const float* __restrict__ beta,
    float* __restrict__ out)
{
    __shared__ float ssc[64], ssh[64];
    __shared__ float spart[128];
    __shared__ float crys[64];
    __shared__ float hred[128];
    const int b = blockIdx.x, tid = threadIdx.x;
    const int f = tid & 63, half = tid >> 6;
    if (tid < 64) {
        float mu  = g_bnsum[2*128 + tid] * (1.0f/NATOMS);
        float var = g_bnsum[2*128 + 64 + tid] * (1.0f/NATOMS) - mu*mu;
        float sc  = gamma[2*64 + tid] * rsqrtf(var + EPSB);
        ssc[tid] = sc;
        ssh[tid] = beta[2*64 + tid] - mu*sc;
    }
    __syncthreads();
    const float sc = ssc[f], sh = ssh[f];
    const int* ci = cidx + b*NPC + half*(NPC/2);
    float a = 0.0f;
    #pragma unroll 4
    for (int i = 0; i < NPC/2; i++)
        a += softplus_f(fmaf(sc, g_y[ci[i]*64 + f], sh));
    spart[tid] = a;
    __syncthreads();
    if (tid < 64) crys[tid] = (spart[tid] + spart[tid + 64]) * (1.0f/NPC);
    __syncthreads();
    float acc = fcb[tid];
    #pragma unroll 8
    for (int k = 0; k < 64; k++) acc = fmaf(crys[k], fcW[k*128 + tid], acc);
    float h = softplus_f(acc);
    out[BQ + b*HFD + tid] = h;
    hred[tid] = h * outW[tid];
    __syncthreads();
    for (int sft = 64; sft > 0; sft >>= 1) {
        if (tid < sft) hred[tid] += hred[tid + sft];
        __syncthreads();
    }
    if (tid == 0) out[b] = hred[0] + outb[0];
}

// ============================================================================
extern "C" void kernel_launch(void* const* d_in, const int* in_sizes, int n_in,
                              void* d_out, int out_size)
{
    const float* atom_fea = (const float*)d_in[0];
    const float* nbr_fea  = (const float*)d_in[1];
    /* d_in[2] = pos (unused: only Y_0 path contributes) */
    const float* emb_W    = (const float*)d_in[3];
    const float* emb_b    = (const float*)d_in[4];
    const float* rW1      = (const float*)d_in[5];
    const float* rb1      = (const float*)d_in[6];
    const float* rW2      = (const float*)d_in[7];
    const float* rb2      = (const float*)d_in[8];
    const float* tpW      = (const float*)d_in[9];
    const float* bn_gamma = (const float*)d_in[10];
    const float* bn_beta  = (const float*)d_in[11];
    const float* fc_W     = (const float*)d_in[12];
    const float* fc_b     = (const float*)d_in[13];
    const float* out_W    = (const float*)d_in[14];
    const float* out_b    = (const float*)d_in[15];
    const int*   nbr_idx  = (const int*)d_in[16];
    const int*   cidx     = (const int*)d_in[17];
    float* out = (float*)d_out;

    setup_kernel<<<1, 256>>>(rW1, rb1, rW2, rb2, tpW);
    embed_kernel<<<(NATOMS + 63)/64, 256>>>(atom_fea, emb_W, emb_b);
    edge_mma_kernel<<<NBLK, 128>>>(nbr_fea);
    for (int l = 0; l < NCONVL; l++) {
        conv_fused_kernel<<<CBLK, 256>>>(nbr_idx, l);
        if (l < 2) bn_kernel<<<592, 256>>>(bn_gamma, bn_beta, l);
    }
    head_kernel<<<BQ, 128>>>(cidx, fc_W, fc_b, out_W, out_b, bn_gamma, bn_beta, out);
}